// round 10
// baseline (speedup 1.0000x reference)
#include <cuda_runtime.h>
#include <cuda_bf16.h>
#include <cstdint>
#include <cstddef>

#define B 8
#define C 512
#define HW 4096
#define M_TOT (B*HW)          // 32768
#define NG 32
#define CPG (C/NG)            // 16
#define GRP_ELEMS (CPG*HW)    // 65536
#define NHEAD 8
#define HD 64
#define EPS_GN 1e-6f
#define SCALE_ATT 8.0f        // sqrt(64), reference MULTIPLIES

// ---------------- scratch ----------------
__device__ float g_xn [B*C*HW];                 // normalized x, (b,c,p) fp32 (residual)
__device__ float g_q  [M_TOT*C];
__device__ float g_k  [M_TOT*C];
__device__ float g_v  [M_TOT*C];
__device__ float g_att[B*NHEAD*NHEAD*HW];       // dots then att, (b,i,j,n)
__device__ __nv_bfloat16 g_xa_hi[M_TOT*C];      // xn row-major (m,k) split
__device__ __nv_bfloat16 g_xa_lo[M_TOT*C];
__device__ __nv_bfloat16 g_w_hi[4*C*C];         // Wq,Wk,Wv,Wp splits (j,k)
__device__ __nv_bfloat16 g_w_lo[4*C*C];
__device__ __nv_bfloat16 g_ao_hi[M_TOT*C];      // attention out split (m,c)
__device__ __nv_bfloat16 g_ao_lo[M_TOT*C];
__device__ float g_mean[B*NG];
__device__ float g_rstd[B*NG];

// ---------------- helpers ----------------
__device__ __forceinline__ uint32_t smem_u32(const void* p) {
    uint32_t a;
    asm("{ .reg .u64 t; cvta.to.shared.u64 t, %1; cvt.u32.u64 %0, t; }" : "=r"(a) : "l"(p));
    return a;
}
#define CP_ASYNC16(s, g)  asm volatile("cp.async.cg.shared.global [%0], [%1], 16;" :: "r"(s), "l"(g))
#define CP_COMMIT()       asm volatile("cp.async.commit_group;" ::: "memory")
#define CP_WAIT(n)        asm volatile("cp.async.wait_group %0;" :: "n"(n) : "memory")

__device__ __forceinline__ void ldsm4(uint32_t* r, uint32_t addr) {
    asm volatile("ldmatrix.sync.aligned.m8n8.x4.shared.b16 {%0,%1,%2,%3}, [%4];"
        : "=r"(r[0]), "=r"(r[1]), "=r"(r[2]), "=r"(r[3]) : "r"(addr));
}
__device__ __forceinline__ void hmma(float* c, const uint32_t* a, const uint32_t* b) {
    asm volatile("mma.sync.aligned.m16n8k16.row.col.f32.bf16.bf16.f32 "
        "{%0,%1,%2,%3}, {%4,%5,%6,%7}, {%8,%9}, {%0,%1,%2,%3};"
        : "+f"(c[0]), "+f"(c[1]), "+f"(c[2]), "+f"(c[3])
        : "r"(a[0]), "r"(a[1]), "r"(a[2]), "r"(a[3]), "r"(b[0]), "r"(b[1]));
}

// ---------------- GroupNorm: stats ----------------
__global__ void gn_stats_kernel(const float* __restrict__ x) {
    int grp = blockIdx.x;
    const float* p = x + (size_t)grp * GRP_ELEMS;
    float s = 0.f, s2 = 0.f;
    for (int i = threadIdx.x; i < GRP_ELEMS; i += blockDim.x) {
        float v = p[i]; s += v; s2 += v * v;
    }
    __shared__ float sh[512], sh2[512];
    sh[threadIdx.x] = s; sh2[threadIdx.x] = s2;
    __syncthreads();
    for (int off = blockDim.x >> 1; off > 0; off >>= 1) {
        if (threadIdx.x < off) {
            sh[threadIdx.x]  += sh[threadIdx.x + off];
            sh2[threadIdx.x] += sh2[threadIdx.x + off];
        }
        __syncthreads();
    }
    if (threadIdx.x == 0) {
        float mean = sh[0] * (1.0f / GRP_ELEMS);
        float var  = sh2[0] * (1.0f / GRP_ELEMS) - mean * mean;
        g_mean[grp] = mean;
        g_rstd[grp] = rsqrtf(var + EPS_GN);
    }
}

// ---------------- fused GroupNorm-apply + transpose + split ----------------
// reads x (b,c,p), writes g_xn (b,c,p) fp32 AND g_xa_hi/lo (m,k) bf16
__global__ void gn_split_kernel(const float* __restrict__ x,
                                const float* __restrict__ gamma,
                                const float* __restrict__ beta) {
    __shared__ float sm[32][33];
    int p0 = blockIdx.x * 32, c0 = blockIdx.y * 32, b = blockIdx.z;
    int tx = threadIdx.x, ty = threadIdx.y;     // (32, 8)
    #pragma unroll
    for (int i = 0; i < 4; i++) {
        int c = c0 + ty + i*8;
        int grp = b*NG + (c >> 4);
        float m = g_mean[grp], r = g_rstd[grp];
        float ga = gamma[c], be = beta[c];
        size_t o = (size_t)b*C*HW + (size_t)c*HW + p0 + tx;
        float v = (x[o] - m) * r * ga + be;
        g_xn[o] = v;
        sm[ty + i*8][tx] = v;
    }
    __syncthreads();
    #pragma unroll
    for (int i = 0; i < 4; i++) {
        int p = p0 + ty + i*8;
        float v = sm[tx][ty + i*8];
        __nv_bfloat16 h = __float2bfloat16(v);
        size_t o = (size_t)(b*HW + p) * C + c0 + tx;
        g_xa_hi[o] = h;
        g_xa_lo[o] = __float2bfloat16(v - __bfloat162float(h));
    }
}

// ---------------- split weights ----------------
__global__ void split_w_kernel(const float* __restrict__ Wq, const float* __restrict__ Wk,
                               const float* __restrict__ Wv, const float* __restrict__ Wp) {
    int idx = blockIdx.x * 256 + threadIdx.x;   // < 4*C*C
    int wsel = idx >> 18;
    int off  = idx & (C*C - 1);
    const float* w = (wsel == 0) ? Wq : (wsel == 1) ? Wk : (wsel == 2) ? Wv : Wp;
    float v = w[off];
    __nv_bfloat16 h = __float2bfloat16(v);
    g_w_hi[idx] = h;
    g_w_lo[idx] = __float2bfloat16(v - __bfloat162float(h));
}

// ---------------- mma.sync bf16x3 GEMM: Y[m,j] = sum_k A[m,k]*W[j,k] ----------------
// GBM=256, GBN=128, GBK=32; 256 threads, warp tile 64x64; 3-stage cp.async pipeline.
// MODE 0: Y fp32 row-major (m, C)
// MODE 1: Y (b,j,p) fp32 + bias[j] + resid[b,j,p]
#define GBM 256
#define GBN 128
#define GBK 32
#define NCH (C/GBK)          // 16
#define NSTAGE 3
#define ASTR 80              // padded row stride (bytes): 32 bf16 + 16B pad
#define OFF_AL 20480         // 256*80
#define OFF_BH 40960
#define OFF_BL 51200         // + 128*80
#define STG 61440            // bytes per stage
#define SMEM_BYTES (NSTAGE*STG)   // 184320

__device__ __forceinline__ void load_stage(uint32_t sb,
        const __nv_bfloat16* Ah, const __nv_bfloat16* Al,
        const __nv_bfloat16* Bh, const __nv_bfloat16* Bl,
        int m0, int n0, int k0, int tid) {
    #pragma unroll
    for (int i = 0; i < 4; i++) {
        int q = tid + i*256;
        int r = q >> 2, c = q & 3;
        uint32_t d = sb + r*ASTR + c*16;
        size_t g = (size_t)(m0 + r) * C + k0 + c*8;
        CP_ASYNC16(d, Ah + g);
        CP_ASYNC16(d + OFF_AL, Al + g);
    }
    #pragma unroll
    for (int i = 0; i < 2; i++) {
        int q = tid + i*256;
        int r = q >> 2, c = q & 3;
        uint32_t d = sb + OFF_BH + r*ASTR + c*16;
        size_t g = (size_t)(n0 + r) * C + k0 + c*8;
        CP_ASYNC16(d, Bh + g);
        CP_ASYNC16(d + (OFF_BL - OFF_BH), Bl + g);
    }
}

template<int MODE>
__global__ __launch_bounds__(256, 1)
void tc_gemm(const __nv_bfloat16* __restrict__ Ah, const __nv_bfloat16* __restrict__ Al,
             const __nv_bfloat16* __restrict__ Bh, const __nv_bfloat16* __restrict__ Bl,
             float* __restrict__ Y, const float* __restrict__ bias,
             const float* __restrict__ resid) {
    extern __shared__ char smc[];
    const uint32_t smb = smem_u32(smc);
    const int tid = threadIdx.x;
    const int lane = tid & 31, wid = tid >> 5;
    const int wm = wid & 3, wn = wid >> 2;        // 4 (m) x 2 (n) warps, tile 64x64
    const int n0 = blockIdx.x * GBN;
    const int m0 = blockIdx.y * GBM;
    const int bb = m0 / HW;
    const int p0 = m0 % HW;

    float acc[4][8][4];
    #pragma unroll
    for (int a = 0; a < 4; a++)
        #pragma unroll
        for (int b = 0; b < 8; b++)
            #pragma unroll
            for (int c = 0; c < 4; c++) acc[a][b][c] = 0.f;

    // ldmatrix lane-relative offsets
    const uint32_t aOff = (wm*64 + (lane & 15)) * ASTR + (lane >> 4) * 16;
    const uint32_t bOff = OFF_BH + (wn*64 + (lane & 7) + ((lane >> 4) & 1) * 8) * ASTR
                        + ((lane >> 3) & 1) * 16;

    load_stage(smb, Ah, Al, Bh, Bl, m0, n0, 0, tid);
    CP_COMMIT();
    load_stage(smb + STG, Ah, Al, Bh, Bl, m0, n0, GBK, tid);
    CP_COMMIT();

    int stg = 0;
    for (int ch = 0; ch < NCH; ch++) {
        CP_WAIT(1);                 // stage ch resident (newest may still fly)
        __syncthreads();
        const uint32_t sb = smb + stg * STG;
        #pragma unroll
        for (int ks = 0; ks < 2; ks++) {
            uint32_t ah[4][4], al[4][4], bh[4][4], bl[4][4];
            #pragma unroll
            for (int mt = 0; mt < 4; mt++) {
                ldsm4(ah[mt], sb + aOff + mt * (16*ASTR) + ks * 32);
                ldsm4(al[mt], sb + OFF_AL + aOff + mt * (16*ASTR) + ks * 32);
            }
            #pragma unroll
            for (int np = 0; np < 4; np++) {
                ldsm4(bh[np], sb + bOff + np * (16*ASTR) + ks * 32);
                ldsm4(bl[np], sb + (OFF_BL - OFF_BH) + bOff + np * (16*ASTR) + ks * 32);
            }
            #pragma unroll
            for (int mt = 0; mt < 4; mt++)
                #pragma unroll
                for (int nt = 0; nt < 8; nt++) {
                    const uint32_t* bhp = &bh[nt >> 1][(nt & 1) * 2];
                    const uint32_t* blp = &bl[nt >> 1][(nt & 1) * 2];
                    hmma(acc[mt][nt], ah[mt], bhp);
                    hmma(acc[mt][nt], ah[mt], blp);
                    hmma(acc[mt][nt], al[mt], bhp);
                }
        }
        __syncthreads();
        if (ch + 2 < NCH) {
            load_stage(smb + ((stg + 2) % NSTAGE) * STG, Ah, Al, Bh, Bl,
                       m0, n0, (ch + 2) * GBK, tid);
            CP_COMMIT();
        }
        stg = (stg + 1) % NSTAGE;
    }

    // ---------------- epilogue ----------------
    const int mrow = wm*64 + (lane >> 2);
    const int ncol = n0 + wn*64 + 2*(lane & 3);
    if (MODE == 0) {
        #pragma unroll
        for (int mt = 0; mt < 4; mt++)
            #pragma unroll
            for (int nt = 0; nt < 8; nt++) {
                int r = m0 + mrow + mt*16;
                int cq = ncol + nt*8;
                float2 v0 = make_float2(acc[mt][nt][0], acc[mt][nt][1]);
                float2 v1 = make_float2(acc[mt][nt][2], acc[mt][nt][3]);
                *(float2*)&Y[(size_t)r * C + cq]       = v0;
                *(float2*)&Y[(size_t)(r + 8) * C + cq] = v1;
            }
    } else {
        #pragma unroll
        for (int mt = 0; mt < 4; mt++)
            #pragma unroll
            for (int nt = 0; nt < 8; nt++) {
                int p = p0 + mrow + mt*16;
                int j = ncol + nt*8;
                float bj0 = bias[j], bj1 = bias[j + 1];
                size_t a00 = (size_t)bb*C*HW + (size_t)j*HW + p;
                Y[a00]          = acc[mt][nt][0] + bj0 + resid[a00];
                Y[a00 + HW]     = acc[mt][nt][1] + bj1 + resid[a00 + HW];
                Y[a00 + 8]      = acc[mt][nt][2] + bj0 + resid[a00 + 8];
                Y[a00 + HW + 8] = acc[mt][nt][3] + bj1 + resid[a00 + HW + 8];
            }
    }
}

// ---------------- dots: warp per (b,n); all 64 (i,j) pairs ----------------
__global__ void dots_kernel() {
    __shared__ float sQ[8][512];
    __shared__ float sK[8][512];
    int w = threadIdx.x >> 5, lane = threadIdx.x & 31;
    int m = blockIdx.x * 8 + w;                 // < 32768
    int b = m >> 12, n = m & 4095;
    const float4* q4 = (const float4*)(g_q + (size_t)m * C);
    const float4* k4 = (const float4*)(g_k + (size_t)m * C);
    #pragma unroll
    for (int i = 0; i < 4; i++) {
        ((float4*)sQ[w])[lane + i*32] = q4[lane + i*32];
        ((float4*)sK[w])[lane + i*32] = k4[lane + i*32];
    }
    __syncwarp();
    #pragma unroll
    for (int t = 0; t < 2; t++) {
        int p = lane + t*32;                    // 0..63
        int i = p >> 3, j = p & 7;
        const float* qi = &sQ[w][i * HD];
        const float* kj = &sK[w][j * HD];
        float acc = 0.f;
        #pragma unroll
        for (int d = 0; d < HD; d++) acc += qi[d] * kj[d];
        g_att[(size_t)(b*64 + p) * HW + n] = acc * SCALE_ATT;
    }
}

// ---------------- softmax over n per (b,i,j) row, in place ----------------
__global__ void softmax_kernel() {
    float* row = g_att + (size_t)blockIdx.x * HW;
    __shared__ float sh[256];
    int tid = threadIdx.x;

    float mx = -1e30f;
    for (int n = tid; n < HW; n += 256) mx = fmaxf(mx, row[n]);
    sh[tid] = mx; __syncthreads();
    for (int off = 128; off > 0; off >>= 1) {
        if (tid < off) sh[tid] = fmaxf(sh[tid], sh[tid + off]);
        __syncthreads();
    }
    mx = sh[0]; __syncthreads();

    float sum = 0.f;
    for (int n = tid; n < HW; n += 256) sum += __expf(row[n] - mx);
    sh[tid] = sum; __syncthreads();
    for (int off = 128; off > 0; off >>= 1) {
        if (tid < off) sh[tid] += sh[tid + off];
        __syncthreads();
    }
    float inv = 1.f / sh[0];

    for (int n = tid; n < HW; n += 256) row[n] = __expf(row[n] - mx) * inv;
}

// ---------------- attv: ao[m, i*64+d] = sum_j att[b,i,j,n] * V[m, j*64+d]; split bf16 ----------------
__global__ void attv_kernel() {
    size_t idx = (size_t)blockIdx.x * 256 + threadIdx.x;  // < M_TOT*C
    int m  = (int)(idx >> 9);
    int cc = (int)(idx & 511);
    int b = m >> 12, n = m & 4095;
    int i = cc >> 6, d = cc & 63;
    const float* att = g_att + ((size_t)(b*64 + i*8)) * HW + n;
    const float* v   = g_v + (size_t)m * C + d;
    float acc = 0.f;
    #pragma unroll
    for (int j = 0; j < NHEAD; j++)
        acc += att[(size_t)j * HW] * v[j * HD];
    __nv_bfloat16 h = __float2bfloat16(acc);
    g_ao_hi[idx] = h;
    g_ao_lo[idx] = __float2bfloat16(acc - __bfloat162float(h));
}

// ---------------- launch ----------------
extern "C" void kernel_launch(void* const* d_in, const int* in_sizes, int n_in,
                              void* d_out, int out_size) {
    const float* x     = (const float*)d_in[0];
    const float* gamma = (const float*)d_in[1];
    const float* beta  = (const float*)d_in[2];
    const float* Wq    = (const float*)d_in[3];
    const float* Wk    = (const float*)d_in[4];
    const float* Wv    = (const float*)d_in[5];
    const float* Wp    = (const float*)d_in[6];
    const float* bp    = (const float*)d_in[7];
    float* out = (float*)d_out;

    float *p_xn, *p_q, *p_k, *p_v;
    __nv_bfloat16 *p_xah, *p_xal, *p_wh, *p_wl, *p_aoh, *p_aol;
    cudaGetSymbolAddress((void**)&p_xn,  g_xn);
    cudaGetSymbolAddress((void**)&p_q,   g_q);
    cudaGetSymbolAddress((void**)&p_k,   g_k);
    cudaGetSymbolAddress((void**)&p_v,   g_v);
    cudaGetSymbolAddress((void**)&p_xah, g_xa_hi);
    cudaGetSymbolAddress((void**)&p_xal, g_xa_lo);
    cudaGetSymbolAddress((void**)&p_wh,  g_w_hi);
    cudaGetSymbolAddress((void**)&p_wl,  g_w_lo);
    cudaGetSymbolAddress((void**)&p_aoh, g_ao_hi);
    cudaGetSymbolAddress((void**)&p_aol, g_ao_lo);

    cudaFuncSetAttribute(tc_gemm<0>, cudaFuncAttributeMaxDynamicSharedMemorySize, SMEM_BYTES);
    cudaFuncSetAttribute(tc_gemm<1>, cudaFuncAttributeMaxDynamicSharedMemorySize, SMEM_BYTES);

    gn_stats_kernel<<<B*NG, 512>>>(x);
    gn_split_kernel<<<dim3(HW/32, C/32, B), dim3(32, 8)>>>(x, gamma, beta);
    split_w_kernel<<<4*C*C/256, 256>>>(Wq, Wk, Wv, Wp);

    dim3 gg(C/GBN, M_TOT/GBM);   // (4, 128)
    tc_gemm<0><<<gg, 256, SMEM_BYTES>>>(p_xah, p_xal, p_wh + 0*C*C, p_wl + 0*C*C, p_q, nullptr, nullptr);
    tc_gemm<0><<<gg, 256, SMEM_BYTES>>>(p_xah, p_xal, p_wh + 1*C*C, p_wl + 1*C*C, p_k, nullptr, nullptr);
    tc_gemm<0><<<gg, 256, SMEM_BYTES>>>(p_xah, p_xal, p_wh + 2*C*C, p_wl + 2*C*C, p_v, nullptr, nullptr);

    dots_kernel<<<M_TOT/8, 256>>>();
    softmax_kernel<<<B*NHEAD*NHEAD, 256>>>();
    attv_kernel<<<(unsigned)(M_TOT*(size_t)C/256), 256>>>();

    tc_gemm<1><<<gg, 256, SMEM_BYTES>>>(p_aoh, p_aol, p_wh + 3*C*C, p_wl + 3*C*C, out, bp, p_xn);
}

// round 11
// speedup vs baseline: 1.0943x; 1.0943x over previous
#include <cuda_runtime.h>
#include <cuda_bf16.h>
#include <cuda_fp16.h>
#include <cstdint>
#include <cstddef>

#define B 8
#define C 512
#define HW 4096
#define M_TOT (B*HW)          // 32768
#define NG 32
#define CPG (C/NG)            // 16
#define GRP_ELEMS (CPG*HW)    // 65536
#define NHEAD 8
#define HD 64
#define EPS_GN 1e-6f
#define SCALE_ATT 8.0f        // sqrt(64), reference MULTIPLIES

// ---------------- scratch ----------------
__device__ float g_xn [B*C*HW];                 // normalized x, (b,c,p) fp32 (residual)
__device__ float g_qk [(size_t)M_TOT*1024];     // [Q | K] row-major, stride 1024
__device__ float g_v  [M_TOT*C];
__device__ float g_att[B*NHEAD*NHEAD*HW];       // dots then att, (b,i,j,n)
__device__ __nv_bfloat16 g_xa_hi[M_TOT*C];      // xn row-major (m,k) bf16 split (QK path)
__device__ __nv_bfloat16 g_xa_lo[M_TOT*C];
__device__ __half g_x16h[M_TOT*C];              // xn row-major fp16 split (V path)
__device__ __half g_x16l[M_TOT*C];
__device__ __nv_bfloat16 g_w_hi[2*C*C];         // [Wq;Wk] bf16 split (j,k)
__device__ __nv_bfloat16 g_w_lo[2*C*C];
__device__ __half g_w16[2*C*C];                 // [Wv;Wp] fp16 (j,k)
__device__ __half g_ao_h[M_TOT*C];              // attention out fp16 split (m,c)
__device__ __half g_ao_l[M_TOT*C];
__device__ float g_mean[B*NG];
__device__ float g_rstd[B*NG];

// ---------------- helpers ----------------
__device__ __forceinline__ uint32_t smem_u32(const void* p) {
    uint32_t a;
    asm("{ .reg .u64 t; cvta.to.shared.u64 t, %1; cvt.u32.u64 %0, t; }" : "=r"(a) : "l"(p));
    return a;
}
#define CP_ASYNC16(s, g)  asm volatile("cp.async.cg.shared.global [%0], [%1], 16;" :: "r"(s), "l"(g))
#define CP_COMMIT()       asm volatile("cp.async.commit_group;" ::: "memory")
#define CP_WAIT(n)        asm volatile("cp.async.wait_group %0;" :: "n"(n) : "memory")

__device__ __forceinline__ void ldsm4(uint32_t* r, uint32_t addr) {
    asm volatile("ldmatrix.sync.aligned.m8n8.x4.shared.b16 {%0,%1,%2,%3}, [%4];"
        : "=r"(r[0]), "=r"(r[1]), "=r"(r[2]), "=r"(r[3]) : "r"(addr));
}
__device__ __forceinline__ void hmma_bf16(float* c, const uint32_t* a, const uint32_t* b) {
    asm volatile("mma.sync.aligned.m16n8k16.row.col.f32.bf16.bf16.f32 "
        "{%0,%1,%2,%3}, {%4,%5,%6,%7}, {%8,%9}, {%0,%1,%2,%3};"
        : "+f"(c[0]), "+f"(c[1]), "+f"(c[2]), "+f"(c[3])
        : "r"(a[0]), "r"(a[1]), "r"(a[2]), "r"(a[3]), "r"(b[0]), "r"(b[1]));
}
__device__ __forceinline__ void hmma_f16(float* c, const uint32_t* a, const uint32_t* b) {
    asm volatile("mma.sync.aligned.m16n8k16.row.col.f32.f16.f16.f32 "
        "{%0,%1,%2,%3}, {%4,%5,%6,%7}, {%8,%9}, {%0,%1,%2,%3};"
        : "+f"(c[0]), "+f"(c[1]), "+f"(c[2]), "+f"(c[3])
        : "r"(a[0]), "r"(a[1]), "r"(a[2]), "r"(a[3]), "r"(b[0]), "r"(b[1]));
}

// ---------------- GroupNorm: stats ----------------
__global__ void gn_stats_kernel(const float* __restrict__ x) {
    int grp = blockIdx.x;
    const float* p = x + (size_t)grp * GRP_ELEMS;
    float s = 0.f, s2 = 0.f;
    for (int i = threadIdx.x; i < GRP_ELEMS; i += blockDim.x) {
        float v = p[i]; s += v; s2 += v * v;
    }
    __shared__ float sh[512], sh2[512];
    sh[threadIdx.x] = s; sh2[threadIdx.x] = s2;
    __syncthreads();
    for (int off = blockDim.x >> 1; off > 0; off >>= 1) {
        if (threadIdx.x < off) {
            sh[threadIdx.x]  += sh[threadIdx.x + off];
            sh2[threadIdx.x] += sh2[threadIdx.x + off];
        }
        __syncthreads();
    }
    if (threadIdx.x == 0) {
        float mean = sh[0] * (1.0f / GRP_ELEMS);
        float var  = sh2[0] * (1.0f / GRP_ELEMS) - mean * mean;
        g_mean[grp] = mean;
        g_rstd[grp] = rsqrtf(var + EPS_GN);
    }
}

// ---------------- fused GroupNorm-apply + transpose + splits ----------------
__global__ void gn_split_kernel(const float* __restrict__ x,
                                const float* __restrict__ gamma,
                                const float* __restrict__ beta) {
    __shared__ float sm[32][33];
    int p0 = blockIdx.x * 32, c0 = blockIdx.y * 32, b = blockIdx.z;
    int tx = threadIdx.x, ty = threadIdx.y;     // (32, 8)
    #pragma unroll
    for (int i = 0; i < 4; i++) {
        int c = c0 + ty + i*8;
        int grp = b*NG + (c >> 4);
        float m = g_mean[grp], r = g_rstd[grp];
        float ga = gamma[c], be = beta[c];
        size_t o = (size_t)b*C*HW + (size_t)c*HW + p0 + tx;
        float v = (x[o] - m) * r * ga + be;
        g_xn[o] = v;
        sm[ty + i*8][tx] = v;
    }
    __syncthreads();
    #pragma unroll
    for (int i = 0; i < 4; i++) {
        int p = p0 + ty + i*8;
        float v = sm[tx][ty + i*8];
        size_t o = (size_t)(b*HW + p) * C + c0 + tx;
        __nv_bfloat16 h = __float2bfloat16(v);
        g_xa_hi[o] = h;
        g_xa_lo[o] = __float2bfloat16(v - __bfloat162float(h));
        __half h16 = __float2half(v);
        g_x16h[o] = h16;
        g_x16l[o] = __float2half(v - __half2float(h16));
    }
}

// ---------------- split weights ----------------
// bf16 hi/lo for [Wq;Wk]; fp16 single for [Wv;Wp]
__global__ void split_w_kernel(const float* __restrict__ Wq, const float* __restrict__ Wk,
                               const float* __restrict__ Wv, const float* __restrict__ Wp) {
    int idx = blockIdx.x * 256 + threadIdx.x;   // < 2*C*C
    int wsel = idx >> 18;
    int off  = idx & (C*C - 1);
    float vqk = (wsel == 0) ? Wq[off] : Wk[off];
    __nv_bfloat16 h = __float2bfloat16(vqk);
    g_w_hi[idx] = h;
    g_w_lo[idx] = __float2bfloat16(vqk - __bfloat162float(h));
    float vvp = (wsel == 0) ? Wv[off] : Wp[off];
    g_w16[idx] = __float2half(vvp);
}

// ================= GEMM 3-term bf16 (QK fused): Y[m, 0..1023] =================
#define GBM 256
#define GBN 128
#define GBK 32
#define NCH (C/GBK)          // 16
#define NSTAGE 3
#define ASTR 80              // padded row stride (bytes): 32 elems*2B + 16B pad
#define OFF_AL 20480         // 256*80
#define OFF_BH 40960
#define OFF_BL 51200         // + 128*80
#define STG 61440
#define SMEM3 (NSTAGE*STG)   // 184320

__device__ __forceinline__ void load_stage3(uint32_t sb,
        const __nv_bfloat16* Ah, const __nv_bfloat16* Al,
        const __nv_bfloat16* Bh, const __nv_bfloat16* Bl,
        int m0, int n0, int k0, int tid) {
    #pragma unroll
    for (int i = 0; i < 4; i++) {
        int q = tid + i*256;
        int r = q >> 2, c = q & 3;
        uint32_t d = sb + r*ASTR + c*16;
        size_t g = (size_t)(m0 + r) * C + k0 + c*8;
        CP_ASYNC16(d, Ah + g);
        CP_ASYNC16(d + OFF_AL, Al + g);
    }
    #pragma unroll
    for (int i = 0; i < 2; i++) {
        int q = tid + i*256;
        int r = q >> 2, c = q & 3;
        uint32_t d = sb + OFF_BH + r*ASTR + c*16;
        size_t g = (size_t)(n0 + r) * C + k0 + c*8;
        CP_ASYNC16(d, Bh + g);
        CP_ASYNC16(d + (OFF_BL - OFF_BH), Bl + g);
    }
}

__global__ __launch_bounds__(256, 1)
void tc_gemm3(const __nv_bfloat16* __restrict__ Ah, const __nv_bfloat16* __restrict__ Al,
              const __nv_bfloat16* __restrict__ Bh, const __nv_bfloat16* __restrict__ Bl,
              float* __restrict__ Y) {
    extern __shared__ char smc[];
    const uint32_t smb = smem_u32(smc);
    const int tid = threadIdx.x;
    const int lane = tid & 31, wid = tid >> 5;
    const int wm = wid & 3, wn = wid >> 2;        // 4 (m) x 2 (n), warp tile 64x64
    const int n0 = blockIdx.x * GBN;              // 0..896 over N=1024
    const int m0 = blockIdx.y * GBM;

    float acc[4][8][4];
    #pragma unroll
    for (int a = 0; a < 4; a++)
        #pragma unroll
        for (int b = 0; b < 8; b++)
            #pragma unroll
            for (int c = 0; c < 4; c++) acc[a][b][c] = 0.f;

    const uint32_t aOff = (wm*64 + (lane & 15)) * ASTR + (lane >> 4) * 16;
    const uint32_t bOff = OFF_BH + (wn*64 + (lane & 7) + ((lane >> 4) & 1) * 8) * ASTR
                        + ((lane >> 3) & 1) * 16;

    load_stage3(smb, Ah, Al, Bh, Bl, m0, n0, 0, tid);
    CP_COMMIT();
    load_stage3(smb + STG, Ah, Al, Bh, Bl, m0, n0, GBK, tid);
    CP_COMMIT();

    int stg = 0;
    for (int ch = 0; ch < NCH; ch++) {
        CP_WAIT(1);
        __syncthreads();
        const uint32_t sb = smb + stg * STG;
        #pragma unroll
        for (int ks = 0; ks < 2; ks++) {
            uint32_t ah[4][4], al[4][4], bh[4][4], bl[4][4];
            #pragma unroll
            for (int mt = 0; mt < 4; mt++) {
                ldsm4(ah[mt], sb + aOff + mt * (16*ASTR) + ks * 32);
                ldsm4(al[mt], sb + OFF_AL + aOff + mt * (16*ASTR) + ks * 32);
            }
            #pragma unroll
            for (int np = 0; np < 4; np++) {
                ldsm4(bh[np], sb + bOff + np * (16*ASTR) + ks * 32);
                ldsm4(bl[np], sb + (OFF_BL - OFF_BH) + bOff + np * (16*ASTR) + ks * 32);
            }
            #pragma unroll
            for (int mt = 0; mt < 4; mt++)
                #pragma unroll
                for (int nt = 0; nt < 8; nt++) {
                    const uint32_t* bhp = &bh[nt >> 1][(nt & 1) * 2];
                    const uint32_t* blp = &bl[nt >> 1][(nt & 1) * 2];
                    hmma_bf16(acc[mt][nt], ah[mt], bhp);
                    hmma_bf16(acc[mt][nt], ah[mt], blp);
                    hmma_bf16(acc[mt][nt], al[mt], bhp);
                }
        }
        __syncthreads();
        if (ch + 2 < NCH) {
            load_stage3(smb + ((stg + 2) % NSTAGE) * STG, Ah, Al, Bh, Bl,
                        m0, n0, (ch + 2) * GBK, tid);
            CP_COMMIT();
        }
        stg = (stg + 1) % NSTAGE;
    }

    const int mrow = wm*64 + (lane >> 2);
    const int ncol = n0 + wn*64 + 2*(lane & 3);
    #pragma unroll
    for (int mt = 0; mt < 4; mt++)
        #pragma unroll
        for (int nt = 0; nt < 8; nt++) {
            int r = m0 + mrow + mt*16;
            int cq = ncol + nt*8;
            float2 v0 = make_float2(acc[mt][nt][0], acc[mt][nt][1]);
            float2 v1 = make_float2(acc[mt][nt][2], acc[mt][nt][3]);
            *(float2*)&Y[(size_t)r * 1024 + cq]       = v0;
            *(float2*)&Y[(size_t)(r + 8) * 1024 + cq] = v1;
        }
}

// ================= GEMM 2-term fp16: Y[m,j] = (A_hi + A_lo) @ W16.T =================
// GBM=256, GBN=64, warp tile 64x32. MODE 0: Y fp32 (m, C). MODE 1: (b,j,p)+bias+resid.
#define G2BN 64
#define OFF2_AL 20480
#define OFF2_B  40960
#define STG2 46080           // 2*20480 + 64*80
#define SMEM2 (NSTAGE*STG2)  // 138240

__device__ __forceinline__ void load_stage2(uint32_t sb,
        const __half* Ah, const __half* Al, const __half* Bw,
        int m0, int n0, int k0, int tid) {
    #pragma unroll
    for (int i = 0; i < 4; i++) {
        int q = tid + i*256;
        int r = q >> 2, c = q & 3;
        uint32_t d = sb + r*ASTR + c*16;
        size_t g = (size_t)(m0 + r) * C + k0 + c*8;
        CP_ASYNC16(d, Ah + g);
        CP_ASYNC16(d + OFF2_AL, Al + g);
    }
    {
        int r = tid >> 2, c = tid & 3;
        uint32_t d = sb + OFF2_B + r*ASTR + c*16;
        size_t g = (size_t)(n0 + r) * C + k0 + c*8;
        CP_ASYNC16(d, Bw + g);
    }
}

template<int MODE>
__global__ __launch_bounds__(256, 1)
void tc_gemm2(const __half* __restrict__ Ah, const __half* __restrict__ Al,
              const __half* __restrict__ Bw,
              float* __restrict__ Y, const float* __restrict__ bias,
              const float* __restrict__ resid) {
    extern __shared__ char smc[];
    const uint32_t smb = smem_u32(smc);
    const int tid = threadIdx.x;
    const int lane = tid & 31, wid = tid >> 5;
    const int wm = wid & 3, wn = wid >> 2;        // 4 (m) x 2 (n), warp tile 64x32
    const int n0 = blockIdx.x * G2BN;
    const int m0 = blockIdx.y * GBM;
    const int bb = m0 / HW;
    const int p0 = m0 % HW;

    float acc[4][4][4];
    #pragma unroll
    for (int a = 0; a < 4; a++)
        #pragma unroll
        for (int b = 0; b < 4; b++)
            #pragma unroll
            for (int c = 0; c < 4; c++) acc[a][b][c] = 0.f;

    const uint32_t aOff = (wm*64 + (lane & 15)) * ASTR + (lane >> 4) * 16;
    const uint32_t bOff = OFF2_B + (wn*32 + (lane & 7) + ((lane >> 4) & 1) * 8) * ASTR
                        + ((lane >> 3) & 1) * 16;

    load_stage2(smb, Ah, Al, Bw, m0, n0, 0, tid);
    CP_COMMIT();
    load_stage2(smb + STG2, Ah, Al, Bw, m0, n0, GBK, tid);
    CP_COMMIT();

    int stg = 0;
    for (int ch = 0; ch < NCH; ch++) {
        CP_WAIT(1);
        __syncthreads();
        const uint32_t sb = smb + stg * STG2;
        #pragma unroll
        for (int ks = 0; ks < 2; ks++) {
            uint32_t ah[4][4], al[4][4], bh[2][4];
            #pragma unroll
            for (int mt = 0; mt < 4; mt++) {
                ldsm4(ah[mt], sb + aOff + mt * (16*ASTR) + ks * 32);
                ldsm4(al[mt], sb + OFF2_AL + aOff + mt * (16*ASTR) + ks * 32);
            }
            #pragma unroll
            for (int np = 0; np < 2; np++)
                ldsm4(bh[np], sb + bOff + np * (16*ASTR) + ks * 32);
            #pragma unroll
            for (int mt = 0; mt < 4; mt++)
                #pragma unroll
                for (int nt = 0; nt < 4; nt++) {
                    const uint32_t* bp = &bh[nt >> 1][(nt & 1) * 2];
                    hmma_f16(acc[mt][nt], ah[mt], bp);
                    hmma_f16(acc[mt][nt], al[mt], bp);
                }
        }
        __syncthreads();
        if (ch + 2 < NCH) {
            load_stage2(smb + ((stg + 2) % NSTAGE) * STG2, Ah, Al, Bw,
                        m0, n0, (ch + 2) * GBK, tid);
            CP_COMMIT();
        }
        stg = (stg + 1) % NSTAGE;
    }

    const int mrow = wm*64 + (lane >> 2);
    const int ncol = n0 + wn*32 + 2*(lane & 3);
    if (MODE == 0) {
        #pragma unroll
        for (int mt = 0; mt < 4; mt++)
            #pragma unroll
            for (int nt = 0; nt < 4; nt++) {
                int r = m0 + mrow + mt*16;
                int cq = ncol + nt*8;
                float2 v0 = make_float2(acc[mt][nt][0], acc[mt][nt][1]);
                float2 v1 = make_float2(acc[mt][nt][2], acc[mt][nt][3]);
                *(float2*)&Y[(size_t)r * C + cq]       = v0;
                *(float2*)&Y[(size_t)(r + 8) * C + cq] = v1;
            }
    } else {
        #pragma unroll
        for (int mt = 0; mt < 4; mt++)
            #pragma unroll
            for (int nt = 0; nt < 4; nt++) {
                int p = p0 + mrow + mt*16;
                int j = ncol + nt*8;
                float bj0 = bias[j], bj1 = bias[j + 1];
                size_t a00 = (size_t)bb*C*HW + (size_t)j*HW + p;
                Y[a00]          = acc[mt][nt][0] + bj0 + resid[a00];
                Y[a00 + HW]     = acc[mt][nt][1] + bj1 + resid[a00 + HW];
                Y[a00 + 8]      = acc[mt][nt][2] + bj0 + resid[a00 + 8];
                Y[a00 + HW + 8] = acc[mt][nt][3] + bj1 + resid[a00 + HW + 8];
            }
    }
}

// ---------------- dots: warp per (b,n); all 64 (i,j) pairs ----------------
__global__ void dots_kernel() {
    __shared__ float sQ[8][512];
    __shared__ float sK[8][512];
    int w = threadIdx.x >> 5, lane = threadIdx.x & 31;
    int m = blockIdx.x * 8 + w;                 // < 32768
    int b = m >> 12, n = m & 4095;
    const float4* q4 = (const float4*)(g_qk + (size_t)m * 1024);
    const float4* k4 = q4 + 128;                // K half of the row
    #pragma unroll
    for (int i = 0; i < 4; i++) {
        ((float4*)sQ[w])[lane + i*32] = q4[lane + i*32];
        ((float4*)sK[w])[lane + i*32] = k4[lane + i*32];
    }
    __syncwarp();
    #pragma unroll
    for (int t = 0; t < 2; t++) {
        int p = lane + t*32;                    // 0..63
        int i = p >> 3, j = p & 7;
        const float* qi = &sQ[w][i * HD];
        const float* kj = &sK[w][j * HD];
        float acc = 0.f;
        #pragma unroll
        for (int d = 0; d < HD; d++) acc += qi[d] * kj[d];
        g_att[(size_t)(b*64 + p) * HW + n] = acc * SCALE_ATT;
    }
}

// ---------------- softmax over n per (b,i,j) row, in place ----------------
__global__ void softmax_kernel() {
    float* row = g_att + (size_t)blockIdx.x * HW;
    __shared__ float sh[256];
    int tid = threadIdx.x;

    float mx = -1e30f;
    for (int n = tid; n < HW; n += 256) mx = fmaxf(mx, row[n]);
    sh[tid] = mx; __syncthreads();
    for (int off = 128; off > 0; off >>= 1) {
        if (tid < off) sh[tid] = fmaxf(sh[tid], sh[tid + off]);
        __syncthreads();
    }
    mx = sh[0]; __syncthreads();

    float sum = 0.f;
    for (int n = tid; n < HW; n += 256) sum += __expf(row[n] - mx);
    sh[tid] = sum; __syncthreads();
    for (int off = 128; off > 0; off >>= 1) {
        if (tid < off) sh[tid] += sh[tid + off];
        __syncthreads();
    }
    float inv = 1.f / sh[0];

    for (int n = tid; n < HW; n += 256) row[n] = __expf(row[n] - mx) * inv;
}

// ---------------- attv: ao[m, i*64+d] = sum_j att[b,i,j,n] * V[m, j*64+d]; fp16 split ----------------
__global__ void attv_kernel() {
    size_t idx = (size_t)blockIdx.x * 256 + threadIdx.x;  // < M_TOT*C
    int m  = (int)(idx >> 9);
    int cc = (int)(idx & 511);
    int b = m >> 12, n = m & 4095;
    int i = cc >> 6, d = cc & 63;
    const float* att = g_att + ((size_t)(b*64 + i*8)) * HW + n;
    const float* v   = g_v + (size_t)m * C + d;
    float acc = 0.f;
    #pragma unroll
    for (int j = 0; j < NHEAD; j++)
        acc += att[(size_t)j * HW] * v[j * HD];
    __half h = __float2half(acc);
    g_ao_h[idx] = h;
    g_ao_l[idx] = __float2half(acc - __half2float(h));
}

// ---------------- launch ----------------
extern "C" void kernel_launch(void* const* d_in, const int* in_sizes, int n_in,
                              void* d_out, int out_size) {
    const float* x     = (const float*)d_in[0];
    const float* gamma = (const float*)d_in[1];
    const float* beta  = (const float*)d_in[2];
    const float* Wq    = (const float*)d_in[3];
    const float* Wk    = (const float*)d_in[4];
    const float* Wv    = (const float*)d_in[5];
    const float* Wp    = (const float*)d_in[6];
    const float* bp    = (const float*)d_in[7];
    float* out = (float*)d_out;

    float *p_xn, *p_qk, *p_v;
    __nv_bfloat16 *p_xah, *p_xal, *p_wh, *p_wl;
    __half *p_x16h, *p_x16l, *p_w16, *p_aoh, *p_aol;
    cudaGetSymbolAddress((void**)&p_xn,   g_xn);
    cudaGetSymbolAddress((void**)&p_qk,   g_qk);
    cudaGetSymbolAddress((void**)&p_v,    g_v);
    cudaGetSymbolAddress((void**)&p_xah,  g_xa_hi);
    cudaGetSymbolAddress((void**)&p_xal,  g_xa_lo);
    cudaGetSymbolAddress((void**)&p_wh,   g_w_hi);
    cudaGetSymbolAddress((void**)&p_wl,   g_w_lo);
    cudaGetSymbolAddress((void**)&p_x16h, g_x16h);
    cudaGetSymbolAddress((void**)&p_x16l, g_x16l);
    cudaGetSymbolAddress((void**)&p_w16,  g_w16);
    cudaGetSymbolAddress((void**)&p_aoh,  g_ao_h);
    cudaGetSymbolAddress((void**)&p_aol,  g_ao_l);

    cudaFuncSetAttribute(tc_gemm3,    cudaFuncAttributeMaxDynamicSharedMemorySize, SMEM3);
    cudaFuncSetAttribute(tc_gemm2<0>, cudaFuncAttributeMaxDynamicSharedMemorySize, SMEM2);
    cudaFuncSetAttribute(tc_gemm2<1>, cudaFuncAttributeMaxDynamicSharedMemorySize, SMEM2);

    gn_stats_kernel<<<B*NG, 512>>>(x);
    gn_split_kernel<<<dim3(HW/32, C/32, B), dim3(32, 8)>>>(x, gamma, beta);
    split_w_kernel<<<2*C*C/256, 256>>>(Wq, Wk, Wv, Wp);

    // fused Q|K GEMM: N = 1024
    dim3 g3(1024/GBN, M_TOT/GBM);   // (8, 128)
    tc_gemm3<<<g3, 256, SMEM3>>>(p_xah, p_xal, p_wh, p_wl, p_qk);

    // V GEMM (fp16 2-term)
    dim3 g2(C/G2BN, M_TOT/GBM);     // (8, 128)
    tc_gemm2<0><<<g2, 256, SMEM2>>>(p_x16h, p_x16l, p_w16, p_v, nullptr, nullptr);

    dots_kernel<<<M_TOT/8, 256>>>();
    softmax_kernel<<<B*NHEAD*NHEAD, 256>>>();
    attv_kernel<<<(unsigned)(M_TOT*(size_t)C/256), 256>>>();

    // proj GEMM (fp16 2-term) + bias + residual
    tc_gemm2<1><<<g2, 256, SMEM2>>>(p_aoh, p_aol, p_w16 + (size_t)C*C, out, bp, p_xn);
}

// round 12
// speedup vs baseline: 1.1583x; 1.0585x over previous
#include <cuda_runtime.h>
#include <cuda_bf16.h>
#include <cuda_fp16.h>
#include <cstdint>
#include <cstddef>

#define B 8
#define C 512
#define HW 4096
#define M_TOT (B*HW)          // 32768
#define NG 32
#define CPG (C/NG)            // 16
#define GRP_ELEMS (CPG*HW)    // 65536
#define NHEAD 8
#define HD 64
#define EPS_GN 1e-6f
#define SCALE_ATT 8.0f        // sqrt(64), reference MULTIPLIES

// ---------------- scratch ----------------
__device__ float g_xn [B*C*HW];                 // normalized x, (b,c,p) fp32 (residual)
__device__ float g_qk [(size_t)M_TOT*1024];     // [Q | K] row-major, stride 1024
__device__ float g_v  [M_TOT*C];
__device__ float g_att[B*NHEAD*NHEAD*HW];       // dots then att, (b,i,j,n)
__device__ __nv_bfloat16 g_xa_hi[M_TOT*C];      // xn row-major (m,k) bf16 split (QK path)
__device__ __nv_bfloat16 g_xa_lo[M_TOT*C];
__device__ __half g_x16h[M_TOT*C];              // xn row-major fp16 split (V path)
__device__ __half g_x16l[M_TOT*C];
__device__ __nv_bfloat16 g_w_hi[2*C*C];         // [Wq;Wk] bf16 split (j,k)
__device__ __nv_bfloat16 g_w_lo[2*C*C];
__device__ __half g_w16[2*C*C];                 // [Wv;Wp] fp16 (j,k)
__device__ __half g_ao_h[M_TOT*C];              // attention out fp16 split (m,c)
__device__ __half g_ao_l[M_TOT*C];
__device__ float g_mean[B*NG];
__device__ float g_rstd[B*NG];

// ---------------- helpers ----------------
__device__ __forceinline__ uint32_t smem_u32(const void* p) {
    uint32_t a;
    asm("{ .reg .u64 t; cvta.to.shared.u64 t, %1; cvt.u32.u64 %0, t; }" : "=r"(a) : "l"(p));
    return a;
}
#define CP_ASYNC16(s, g)  asm volatile("cp.async.cg.shared.global [%0], [%1], 16;" :: "r"(s), "l"(g))
#define CP_COMMIT()       asm volatile("cp.async.commit_group;" ::: "memory")
#define CP_WAIT(n)        asm volatile("cp.async.wait_group %0;" :: "n"(n) : "memory")

__device__ __forceinline__ void ldsm4(uint32_t* r, uint32_t addr) {
    asm volatile("ldmatrix.sync.aligned.m8n8.x4.shared.b16 {%0,%1,%2,%3}, [%4];"
        : "=r"(r[0]), "=r"(r[1]), "=r"(r[2]), "=r"(r[3]) : "r"(addr));
}
__device__ __forceinline__ void hmma_bf16(float* c, const uint32_t* a, const uint32_t* b) {
    asm volatile("mma.sync.aligned.m16n8k16.row.col.f32.bf16.bf16.f32 "
        "{%0,%1,%2,%3}, {%4,%5,%6,%7}, {%8,%9}, {%0,%1,%2,%3};"
        : "+f"(c[0]), "+f"(c[1]), "+f"(c[2]), "+f"(c[3])
        : "r"(a[0]), "r"(a[1]), "r"(a[2]), "r"(a[3]), "r"(b[0]), "r"(b[1]));
}
__device__ __forceinline__ void hmma_f16(float* c, const uint32_t* a, const uint32_t* b) {
    asm volatile("mma.sync.aligned.m16n8k16.row.col.f32.f16.f16.f32 "
        "{%0,%1,%2,%3}, {%4,%5,%6,%7}, {%8,%9}, {%0,%1,%2,%3};"
        : "+f"(c[0]), "+f"(c[1]), "+f"(c[2]), "+f"(c[3])
        : "r"(a[0]), "r"(a[1]), "r"(a[2]), "r"(a[3]), "r"(b[0]), "r"(b[1]));
}

// ---------------- GroupNorm: stats ----------------
__global__ void gn_stats_kernel(const float* __restrict__ x) {
    int grp = blockIdx.x;
    const float* p = x + (size_t)grp * GRP_ELEMS;
    float s = 0.f, s2 = 0.f;
    for (int i = threadIdx.x; i < GRP_ELEMS; i += blockDim.x) {
        float v = p[i]; s += v; s2 += v * v;
    }
    __shared__ float sh[512], sh2[512];
    sh[threadIdx.x] = s; sh2[threadIdx.x] = s2;
    __syncthreads();
    for (int off = blockDim.x >> 1; off > 0; off >>= 1) {
        if (threadIdx.x < off) {
            sh[threadIdx.x]  += sh[threadIdx.x + off];
            sh2[threadIdx.x] += sh2[threadIdx.x + off];
        }
        __syncthreads();
    }
    if (threadIdx.x == 0) {
        float mean = sh[0] * (1.0f / GRP_ELEMS);
        float var  = sh2[0] * (1.0f / GRP_ELEMS) - mean * mean;
        g_mean[grp] = mean;
        g_rstd[grp] = rsqrtf(var + EPS_GN);
    }
}

// ---------------- fused GroupNorm-apply + transpose + splits ----------------
__global__ void gn_split_kernel(const float* __restrict__ x,
                                const float* __restrict__ gamma,
                                const float* __restrict__ beta) {
    __shared__ float sm[32][33];
    int p0 = blockIdx.x * 32, c0 = blockIdx.y * 32, b = blockIdx.z;
    int tx = threadIdx.x, ty = threadIdx.y;     // (32, 8)
    #pragma unroll
    for (int i = 0; i < 4; i++) {
        int c = c0 + ty + i*8;
        int grp = b*NG + (c >> 4);
        float m = g_mean[grp], r = g_rstd[grp];
        float ga = gamma[c], be = beta[c];
        size_t o = (size_t)b*C*HW + (size_t)c*HW + p0 + tx;
        float v = (x[o] - m) * r * ga + be;
        g_xn[o] = v;
        sm[ty + i*8][tx] = v;
    }
    __syncthreads();
    #pragma unroll
    for (int i = 0; i < 4; i++) {
        int p = p0 + ty + i*8;
        float v = sm[tx][ty + i*8];
        size_t o = (size_t)(b*HW + p) * C + c0 + tx;
        __nv_bfloat16 h = __float2bfloat16(v);
        g_xa_hi[o] = h;
        g_xa_lo[o] = __float2bfloat16(v - __bfloat162float(h));
        __half h16 = __float2half(v);
        g_x16h[o] = h16;
        g_x16l[o] = __float2half(v - __half2float(h16));
    }
}

// ---------------- split weights ----------------
__global__ void split_w_kernel(const float* __restrict__ Wq, const float* __restrict__ Wk,
                               const float* __restrict__ Wv, const float* __restrict__ Wp) {
    int idx = blockIdx.x * 256 + threadIdx.x;   // < 2*C*C
    int wsel = idx >> 18;
    int off  = idx & (C*C - 1);
    float vqk = (wsel == 0) ? Wq[off] : Wk[off];
    __nv_bfloat16 h = __float2bfloat16(vqk);
    g_w_hi[idx] = h;
    g_w_lo[idx] = __float2bfloat16(vqk - __bfloat162float(h));
    float vvp = (wsel == 0) ? Wv[off] : Wp[off];
    g_w16[idx] = __float2half(vvp);
}

// ================= GEMM 3-term bf16 (QK fused): Y[m, 0..1023] =================
#define GBM 256
#define GBN 128
#define GBK 32
#define NCH (C/GBK)          // 16
#define NSTAGE 3
#define ASTR 80
#define OFF_AL 20480         // 256*80
#define OFF_BH 40960
#define OFF_BL 51200
#define STG 61440
#define SMEM3 (NSTAGE*STG)   // 184320

__device__ __forceinline__ void load_stage3(uint32_t sb,
        const __nv_bfloat16* Ah, const __nv_bfloat16* Al,
        const __nv_bfloat16* Bh, const __nv_bfloat16* Bl,
        int m0, int n0, int k0, int tid) {
    #pragma unroll
    for (int i = 0; i < 4; i++) {
        int q = tid + i*256;
        int r = q >> 2, c = q & 3;
        uint32_t d = sb + r*ASTR + c*16;
        size_t g = (size_t)(m0 + r) * C + k0 + c*8;
        CP_ASYNC16(d, Ah + g);
        CP_ASYNC16(d + OFF_AL, Al + g);
    }
    #pragma unroll
    for (int i = 0; i < 2; i++) {
        int q = tid + i*256;
        int r = q >> 2, c = q & 3;
        uint32_t d = sb + OFF_BH + r*ASTR + c*16;
        size_t g = (size_t)(n0 + r) * C + k0 + c*8;
        CP_ASYNC16(d, Bh + g);
        CP_ASYNC16(d + (OFF_BL - OFF_BH), Bl + g);
    }
}

__global__ __launch_bounds__(256, 1)
void tc_gemm3(const __nv_bfloat16* __restrict__ Ah, const __nv_bfloat16* __restrict__ Al,
              const __nv_bfloat16* __restrict__ Bh, const __nv_bfloat16* __restrict__ Bl,
              float* __restrict__ Y) {
    extern __shared__ char smc[];
    const uint32_t smb = smem_u32(smc);
    const int tid = threadIdx.x;
    const int lane = tid & 31, wid = tid >> 5;
    const int wm = wid & 3, wn = wid >> 2;        // 4x2 warps, warp tile 64x64
    const int n0 = blockIdx.x * GBN;
    const int m0 = blockIdx.y * GBM;

    float acc[4][8][4];
    #pragma unroll
    for (int a = 0; a < 4; a++)
        #pragma unroll
        for (int b = 0; b < 8; b++)
            #pragma unroll
            for (int c = 0; c < 4; c++) acc[a][b][c] = 0.f;

    const uint32_t aOff = (wm*64 + (lane & 15)) * ASTR + (lane >> 4) * 16;
    const uint32_t bOff = OFF_BH + (wn*64 + (lane & 7) + ((lane >> 4) & 1) * 8) * ASTR
                        + ((lane >> 3) & 1) * 16;

    load_stage3(smb, Ah, Al, Bh, Bl, m0, n0, 0, tid);
    CP_COMMIT();
    load_stage3(smb + STG, Ah, Al, Bh, Bl, m0, n0, GBK, tid);
    CP_COMMIT();

    int stg = 0;
    for (int ch = 0; ch < NCH; ch++) {
        if (ch < NCH - 1) { CP_WAIT(1); } else { CP_WAIT(0); }
        __syncthreads();
        // prefetch stage ch+2 into the buffer drained at chunk ch-1
        if (ch + 2 < NCH) {
            int ps = stg + 2; if (ps >= NSTAGE) ps -= NSTAGE;
            load_stage3(smb + ps * STG, Ah, Al, Bh, Bl, m0, n0, (ch + 2) * GBK, tid);
            CP_COMMIT();
        }
        const uint32_t sb = smb + stg * STG;
        #pragma unroll
        for (int ks = 0; ks < 2; ks++) {
            uint32_t ah[4][4], al[4][4], bh[4][4], bl[4][4];
            #pragma unroll
            for (int mt = 0; mt < 4; mt++) {
                ldsm4(ah[mt], sb + aOff + mt * (16*ASTR) + ks * 32);
                ldsm4(al[mt], sb + OFF_AL + aOff + mt * (16*ASTR) + ks * 32);
            }
            #pragma unroll
            for (int np = 0; np < 4; np++) {
                ldsm4(bh[np], sb + bOff + np * (16*ASTR) + ks * 32);
                ldsm4(bl[np], sb + (OFF_BL - OFF_BH) + bOff + np * (16*ASTR) + ks * 32);
            }
            // term-major order: 32 independent MMAs between accumulator reuses
            #pragma unroll
            for (int mt = 0; mt < 4; mt++)
                #pragma unroll
                for (int nt = 0; nt < 8; nt++)
                    hmma_bf16(acc[mt][nt], ah[mt], &bh[nt >> 1][(nt & 1) * 2]);
            #pragma unroll
            for (int mt = 0; mt < 4; mt++)
                #pragma unroll
                for (int nt = 0; nt < 8; nt++)
                    hmma_bf16(acc[mt][nt], ah[mt], &bl[nt >> 1][(nt & 1) * 2]);
            #pragma unroll
            for (int mt = 0; mt < 4; mt++)
                #pragma unroll
                for (int nt = 0; nt < 8; nt++)
                    hmma_bf16(acc[mt][nt], al[mt], &bh[nt >> 1][(nt & 1) * 2]);
        }
        stg++; if (stg == NSTAGE) stg = 0;
    }

    const int mrow = wm*64 + (lane >> 2);
    const int ncol = n0 + wn*64 + 2*(lane & 3);
    #pragma unroll
    for (int mt = 0; mt < 4; mt++)
        #pragma unroll
        for (int nt = 0; nt < 8; nt++) {
            int r = m0 + mrow + mt*16;
            int cq = ncol + nt*8;
            float2 v0 = make_float2(acc[mt][nt][0], acc[mt][nt][1]);
            float2 v1 = make_float2(acc[mt][nt][2], acc[mt][nt][3]);
            *(float2*)&Y[(size_t)r * 1024 + cq]       = v0;
            *(float2*)&Y[(size_t)(r + 8) * 1024 + cq] = v1;
        }
}

// ================= GEMM 2-term fp16: Y = (A_hi + A_lo) @ W16.T =================
// GBM=256, GBN=128, warp tile 64x64, same pipeline as gemm3.
#define OFF2_AL 20480
#define OFF2_B  40960
#define STG2 51200           // 2*20480 + 128*80
#define SMEM2 (NSTAGE*STG2)  // 153600

__device__ __forceinline__ void load_stage2(uint32_t sb,
        const __half* Ah, const __half* Al, const __half* Bw,
        int m0, int n0, int k0, int tid) {
    #pragma unroll
    for (int i = 0; i < 4; i++) {
        int q = tid + i*256;
        int r = q >> 2, c = q & 3;
        uint32_t d = sb + r*ASTR + c*16;
        size_t g = (size_t)(m0 + r) * C + k0 + c*8;
        CP_ASYNC16(d, Ah + g);
        CP_ASYNC16(d + OFF2_AL, Al + g);
    }
    #pragma unroll
    for (int i = 0; i < 2; i++) {
        int q = tid + i*256;
        int r = q >> 2, c = q & 3;
        uint32_t d = sb + OFF2_B + r*ASTR + c*16;
        size_t g = (size_t)(n0 + r) * C + k0 + c*8;
        CP_ASYNC16(d, Bw + g);
    }
}

template<int MODE>
__global__ __launch_bounds__(256, 1)
void tc_gemm2(const __half* __restrict__ Ah, const __half* __restrict__ Al,
              const __half* __restrict__ Bw,
              float* __restrict__ Y, const float* __restrict__ bias,
              const float* __restrict__ resid) {
    extern __shared__ char smc[];
    const uint32_t smb = smem_u32(smc);
    const int tid = threadIdx.x;
    const int lane = tid & 31, wid = tid >> 5;
    const int wm = wid & 3, wn = wid >> 2;        // 4x2 warps, warp tile 64x64
    const int n0 = blockIdx.x * GBN;
    const int m0 = blockIdx.y * GBM;
    const int bb = m0 / HW;
    const int p0 = m0 % HW;

    float acc[4][8][4];
    #pragma unroll
    for (int a = 0; a < 4; a++)
        #pragma unroll
        for (int b = 0; b < 8; b++)
            #pragma unroll
            for (int c = 0; c < 4; c++) acc[a][b][c] = 0.f;

    const uint32_t aOff = (wm*64 + (lane & 15)) * ASTR + (lane >> 4) * 16;
    const uint32_t bOff = OFF2_B + (wn*64 + (lane & 7) + ((lane >> 4) & 1) * 8) * ASTR
                        + ((lane >> 3) & 1) * 16;

    load_stage2(smb, Ah, Al, Bw, m0, n0, 0, tid);
    CP_COMMIT();
    load_stage2(smb + STG2, Ah, Al, Bw, m0, n0, GBK, tid);
    CP_COMMIT();

    int stg = 0;
    for (int ch = 0; ch < NCH; ch++) {
        if (ch < NCH - 1) { CP_WAIT(1); } else { CP_WAIT(0); }
        __syncthreads();
        if (ch + 2 < NCH) {
            int ps = stg + 2; if (ps >= NSTAGE) ps -= NSTAGE;
            load_stage2(smb + ps * STG2, Ah, Al, Bw, m0, n0, (ch + 2) * GBK, tid);
            CP_COMMIT();
        }
        const uint32_t sb = smb + stg * STG2;
        #pragma unroll
        for (int ks = 0; ks < 2; ks++) {
            uint32_t ah[4][4], al[4][4], bh[4][4];
            #pragma unroll
            for (int mt = 0; mt < 4; mt++) {
                ldsm4(ah[mt], sb + aOff + mt * (16*ASTR) + ks * 32);
                ldsm4(al[mt], sb + OFF2_AL + aOff + mt * (16*ASTR) + ks * 32);
            }
            #pragma unroll
            for (int np = 0; np < 4; np++)
                ldsm4(bh[np], sb + bOff + np * (16*ASTR) + ks * 32);
            #pragma unroll
            for (int mt = 0; mt < 4; mt++)
                #pragma unroll
                for (int nt = 0; nt < 8; nt++)
                    hmma_f16(acc[mt][nt], ah[mt], &bh[nt >> 1][(nt & 1) * 2]);
            #pragma unroll
            for (int mt = 0; mt < 4; mt++)
                #pragma unroll
                for (int nt = 0; nt < 8; nt++)
                    hmma_f16(acc[mt][nt], al[mt], &bh[nt >> 1][(nt & 1) * 2]);
        }
        stg++; if (stg == NSTAGE) stg = 0;
    }

    const int mrow = wm*64 + (lane >> 2);
    const int ncol = n0 + wn*64 + 2*(lane & 3);
    if (MODE == 0) {
        #pragma unroll
        for (int mt = 0; mt < 4; mt++)
            #pragma unroll
            for (int nt = 0; nt < 8; nt++) {
                int r = m0 + mrow + mt*16;
                int cq = ncol + nt*8;
                float2 v0 = make_float2(acc[mt][nt][0], acc[mt][nt][1]);
                float2 v1 = make_float2(acc[mt][nt][2], acc[mt][nt][3]);
                *(float2*)&Y[(size_t)r * C + cq]       = v0;
                *(float2*)&Y[(size_t)(r + 8) * C + cq] = v1;
            }
    } else {
        #pragma unroll
        for (int mt = 0; mt < 4; mt++)
            #pragma unroll
            for (int nt = 0; nt < 8; nt++) {
                int p = p0 + mrow + mt*16;
                int j = ncol + nt*8;
                float bj0 = bias[j], bj1 = bias[j + 1];
                size_t a00 = (size_t)bb*C*HW + (size_t)j*HW + p;
                Y[a00]          = acc[mt][nt][0] + bj0 + resid[a00];
                Y[a00 + HW]     = acc[mt][nt][1] + bj1 + resid[a00 + HW];
                Y[a00 + 8]      = acc[mt][nt][2] + bj0 + resid[a00 + 8];
                Y[a00 + HW + 8] = acc[mt][nt][3] + bj1 + resid[a00 + HW + 8];
            }
    }
}

// ---------------- dots: warp per (b,n); all 64 (i,j) pairs ----------------
__global__ void dots_kernel() {
    __shared__ float sQ[8][512];
    __shared__ float sK[8][512];
    int w = threadIdx.x >> 5, lane = threadIdx.x & 31;
    int m = blockIdx.x * 8 + w;                 // < 32768
    int b = m >> 12, n = m & 4095;
    const float4* q4 = (const float4*)(g_qk + (size_t)m * 1024);
    const float4* k4 = q4 + 128;                // K half of the row
    #pragma unroll
    for (int i = 0; i < 4; i++) {
        ((float4*)sQ[w])[lane + i*32] = q4[lane + i*32];
        ((float4*)sK[w])[lane + i*32] = k4[lane + i*32];
    }
    __syncwarp();
    #pragma unroll
    for (int t = 0; t < 2; t++) {
        int p = lane + t*32;                    // 0..63
        int i = p >> 3, j = p & 7;
        const float* qi = &sQ[w][i * HD];
        const float* kj = &sK[w][j * HD];
        float acc = 0.f;
        #pragma unroll
        for (int d = 0; d < HD; d++) acc += qi[d] * kj[d];
        g_att[(size_t)(b*64 + p) * HW + n] = acc * SCALE_ATT;
    }
}

// ---------------- softmax over n per (b,i,j) row, in place ----------------
__global__ void softmax_kernel() {
    float* row = g_att + (size_t)blockIdx.x * HW;
    __shared__ float sh[256];
    int tid = threadIdx.x;

    float mx = -1e30f;
    for (int n = tid; n < HW; n += 256) mx = fmaxf(mx, row[n]);
    sh[tid] = mx; __syncthreads();
    for (int off = 128; off > 0; off >>= 1) {
        if (tid < off) sh[tid] = fmaxf(sh[tid], sh[tid + off]);
        __syncthreads();
    }
    mx = sh[0]; __syncthreads();

    float sum = 0.f;
    for (int n = tid; n < HW; n += 256) sum += __expf(row[n] - mx);
    sh[tid] = sum; __syncthreads();
    for (int off = 128; off > 0; off >>= 1) {
        if (tid < off) sh[tid] += sh[tid + off];
        __syncthreads();
    }
    float inv = 1.f / sh[0];

    for (int n = tid; n < HW; n += 256) row[n] = __expf(row[n] - mx) * inv;
}

// ---------------- attv: ao[m, i*64+d] = sum_j att[b,i,j,n] * V[m, j*64+d]; fp16 split ----------------
__global__ void attv_kernel() {
    size_t idx = (size_t)blockIdx.x * 256 + threadIdx.x;  // < M_TOT*C
    int m  = (int)(idx >> 9);
    int cc = (int)(idx & 511);
    int b = m >> 12, n = m & 4095;
    int i = cc >> 6, d = cc & 63;
    const float* att = g_att + ((size_t)(b*64 + i*8)) * HW + n;
    const float* v   = g_v + (size_t)m * C + d;
    float acc = 0.f;
    #pragma unroll
    for (int j = 0; j < NHEAD; j++)
        acc += att[(size_t)j * HW] * v[j * HD];
    __half h = __float2half(acc);
    g_ao_h[idx] = h;
    g_ao_l[idx] = __float2half(acc - __half2float(h));
}

// ---------------- launch ----------------
extern "C" void kernel_launch(void* const* d_in, const int* in_sizes, int n_in,
                              void* d_out, int out_size) {
    const float* x     = (const float*)d_in[0];
    const float* gamma = (const float*)d_in[1];
    const float* beta  = (const float*)d_in[2];
    const float* Wq    = (const float*)d_in[3];
    const float* Wk    = (const float*)d_in[4];
    const float* Wv    = (const float*)d_in[5];
    const float* Wp    = (const float*)d_in[6];
    const float* bp    = (const float*)d_in[7];
    float* out = (float*)d_out;

    float *p_xn, *p_qk, *p_v;
    __nv_bfloat16 *p_xah, *p_xal, *p_wh, *p_wl;
    __half *p_x16h, *p_x16l, *p_w16, *p_aoh, *p_aol;
    cudaGetSymbolAddress((void**)&p_xn,   g_xn);
    cudaGetSymbolAddress((void**)&p_qk,   g_qk);
    cudaGetSymbolAddress((void**)&p_v,    g_v);
    cudaGetSymbolAddress((void**)&p_xah,  g_xa_hi);
    cudaGetSymbolAddress((void**)&p_xal,  g_xa_lo);
    cudaGetSymbolAddress((void**)&p_wh,   g_w_hi);
    cudaGetSymbolAddress((void**)&p_wl,   g_w_lo);
    cudaGetSymbolAddress((void**)&p_x16h, g_x16h);
    cudaGetSymbolAddress((void**)&p_x16l, g_x16l);
    cudaGetSymbolAddress((void**)&p_w16,  g_w16);
    cudaGetSymbolAddress((void**)&p_aoh,  g_ao_h);
    cudaGetSymbolAddress((void**)&p_aol,  g_ao_l);

    cudaFuncSetAttribute(tc_gemm3,    cudaFuncAttributeMaxDynamicSharedMemorySize, SMEM3);
    cudaFuncSetAttribute(tc_gemm2<0>, cudaFuncAttributeMaxDynamicSharedMemorySize, SMEM2);
    cudaFuncSetAttribute(tc_gemm2<1>, cudaFuncAttributeMaxDynamicSharedMemorySize, SMEM2);

    gn_stats_kernel<<<B*NG, 512>>>(x);
    gn_split_kernel<<<dim3(HW/32, C/32, B), dim3(32, 8)>>>(x, gamma, beta);
    split_w_kernel<<<2*C*C/256, 256>>>(Wq, Wk, Wv, Wp);

    // fused Q|K GEMM: N = 1024
    dim3 g3(1024/GBN, M_TOT/GBM);   // (8, 128)
    tc_gemm3<<<g3, 256, SMEM3>>>(p_xah, p_xal, p_wh, p_wl, p_qk);

    // V GEMM (fp16 2-term)
    dim3 g2(C/GBN, M_TOT/GBM);      // (4, 128)
    tc_gemm2<0><<<g2, 256, SMEM2>>>(p_x16h, p_x16l, p_w16, p_v, nullptr, nullptr);

    dots_kernel<<<M_TOT/8, 256>>>();
    softmax_kernel<<<B*NHEAD*NHEAD, 256>>>();
    attv_kernel<<<(unsigned)(M_TOT*(size_t)C/256), 256>>>();

    // proj GEMM (fp16 2-term) + bias + residual
    tc_gemm2<1><<<g2, 256, SMEM2>>>(p_aoh, p_aol, p_w16 + (size_t)C*C, out, bp, p_xn);
}

// round 13
// speedup vs baseline: 1.3263x; 1.1450x over previous
#include <cuda_runtime.h>
#include <cuda_bf16.h>
#include <cuda_fp16.h>
#include <cstdint>
#include <cstddef>

#define B 8
#define C 512
#define HW 4096
#define M_TOT (B*HW)          // 32768
#define NG 32
#define CPG (C/NG)            // 16
#define GRP_ELEMS (CPG*HW)    // 65536
#define NHEAD 8
#define HD 64
#define EPS_GN 1e-6f
#define SCALE_ATT 8.0f        // sqrt(64), reference MULTIPLIES

// ---------------- scratch ----------------
__device__ float g_xn [B*C*HW];                 // normalized x, (b,c,p) fp32 (residual)
__device__ float g_qk [(size_t)M_TOT*1024];     // [Q | K] row-major, stride 1024
__device__ float g_v  [M_TOT*C];
__device__ float g_att[B*NHEAD*NHEAD*HW];       // dots then att, (b,i,j,n)
__device__ __nv_bfloat16 g_xa_hi[M_TOT*C];      // xn row-major (m,k) bf16 split (QK path)
__device__ __nv_bfloat16 g_xa_lo[M_TOT*C];
__device__ __half g_x16h[M_TOT*C];              // xn row-major fp16 (V path)
__device__ __nv_bfloat16 g_w_hi[2*C*C];         // [Wq;Wk] bf16 split (j,k)
__device__ __nv_bfloat16 g_w_lo[2*C*C];
__device__ __half g_w16[2*C*C];                 // [Wv;Wp] fp16 (j,k)
__device__ __half g_ao_h[M_TOT*C];              // attention out fp16 (m,c)
__device__ float g_mean[B*NG];
__device__ float g_rstd[B*NG];

// ---------------- helpers ----------------
__device__ __forceinline__ uint32_t smem_u32(const void* p) {
    uint32_t a;
    asm("{ .reg .u64 t; cvta.to.shared.u64 t, %1; cvt.u32.u64 %0, t; }" : "=r"(a) : "l"(p));
    return a;
}
#define CP_ASYNC16(s, g)  asm volatile("cp.async.cg.shared.global [%0], [%1], 16;" :: "r"(s), "l"(g))
#define CP_COMMIT()       asm volatile("cp.async.commit_group;" ::: "memory")
#define CP_WAIT(n)        asm volatile("cp.async.wait_group %0;" :: "n"(n) : "memory")

__device__ __forceinline__ void ldsm4(uint32_t* r, uint32_t addr) {
    asm volatile("ldmatrix.sync.aligned.m8n8.x4.shared.b16 {%0,%1,%2,%3}, [%4];"
        : "=r"(r[0]), "=r"(r[1]), "=r"(r[2]), "=r"(r[3]) : "r"(addr));
}
__device__ __forceinline__ void hmma_bf16(float* c, const uint32_t* a, const uint32_t* b) {
    asm volatile("mma.sync.aligned.m16n8k16.row.col.f32.bf16.bf16.f32 "
        "{%0,%1,%2,%3}, {%4,%5,%6,%7}, {%8,%9}, {%0,%1,%2,%3};"
        : "+f"(c[0]), "+f"(c[1]), "+f"(c[2]), "+f"(c[3])
        : "r"(a[0]), "r"(a[1]), "r"(a[2]), "r"(a[3]), "r"(b[0]), "r"(b[1]));
}
__device__ __forceinline__ void hmma_f16(float* c, const uint32_t* a, const uint32_t* b) {
    asm volatile("mma.sync.aligned.m16n8k16.row.col.f32.f16.f16.f32 "
        "{%0,%1,%2,%3}, {%4,%5,%6,%7}, {%8,%9}, {%0,%1,%2,%3};"
        : "+f"(c[0]), "+f"(c[1]), "+f"(c[2]), "+f"(c[3])
        : "r"(a[0]), "r"(a[1]), "r"(a[2]), "r"(a[3]), "r"(b[0]), "r"(b[1]));
}

// ---------------- GroupNorm: stats ----------------
__global__ void gn_stats_kernel(const float* __restrict__ x) {
    int grp = blockIdx.x;
    const float* p = x + (size_t)grp * GRP_ELEMS;
    float s = 0.f, s2 = 0.f;
    for (int i = threadIdx.x; i < GRP_ELEMS; i += blockDim.x) {
        float v = p[i]; s += v; s2 += v * v;
    }
    __shared__ float sh[512], sh2[512];
    sh[threadIdx.x] = s; sh2[threadIdx.x] = s2;
    __syncthreads();
    for (int off = blockDim.x >> 1; off > 0; off >>= 1) {
        if (threadIdx.x < off) {
            sh[threadIdx.x]  += sh[threadIdx.x + off];
            sh2[threadIdx.x] += sh2[threadIdx.x + off];
        }
        __syncthreads();
    }
    if (threadIdx.x == 0) {
        float mean = sh[0] * (1.0f / GRP_ELEMS);
        float var  = sh2[0] * (1.0f / GRP_ELEMS) - mean * mean;
        g_mean[grp] = mean;
        g_rstd[grp] = rsqrtf(var + EPS_GN);
    }
}

// ---------------- fused GroupNorm-apply + transpose + splits ----------------
__global__ void gn_split_kernel(const float* __restrict__ x,
                                const float* __restrict__ gamma,
                                const float* __restrict__ beta) {
    __shared__ float sm[32][33];
    int p0 = blockIdx.x * 32, c0 = blockIdx.y * 32, b = blockIdx.z;
    int tx = threadIdx.x, ty = threadIdx.y;     // (32, 8)
    #pragma unroll
    for (int i = 0; i < 4; i++) {
        int c = c0 + ty + i*8;
        int grp = b*NG + (c >> 4);
        float m = g_mean[grp], r = g_rstd[grp];
        float ga = gamma[c], be = beta[c];
        size_t o = (size_t)b*C*HW + (size_t)c*HW + p0 + tx;
        float v = (x[o] - m) * r * ga + be;
        g_xn[o] = v;
        sm[ty + i*8][tx] = v;
    }
    __syncthreads();
    #pragma unroll
    for (int i = 0; i < 4; i++) {
        int p = p0 + ty + i*8;
        float v = sm[tx][ty + i*8];
        size_t o = (size_t)(b*HW + p) * C + c0 + tx;
        __nv_bfloat16 h = __float2bfloat16(v);
        g_xa_hi[o] = h;
        g_xa_lo[o] = __float2bfloat16(v - __bfloat162float(h));
        g_x16h[o] = __float2half(v);
    }
}

// ---------------- split weights ----------------
__global__ void split_w_kernel(const float* __restrict__ Wq, const float* __restrict__ Wk,
                               const float* __restrict__ Wv, const float* __restrict__ Wp) {
    int idx = blockIdx.x * 256 + threadIdx.x;   // < 2*C*C
    int wsel = idx >> 18;
    int off  = idx & (C*C - 1);
    float vqk = (wsel == 0) ? Wq[off] : Wk[off];
    __nv_bfloat16 h = __float2bfloat16(vqk);
    g_w_hi[idx] = h;
    g_w_lo[idx] = __float2bfloat16(vqk - __bfloat162float(h));
    float vvp = (wsel == 0) ? Wv[off] : Wp[off];
    g_w16[idx] = __float2half(vvp);
}

// ================= GEMM 3-term bf16 (QK fused): Y[m, 0..1023] =================
#define GBM 256
#define GBN 128
#define GBK 32
#define NCH (C/GBK)          // 16
#define NSTAGE 3
#define ASTR 80
#define OFF_AL 20480         // 256*80
#define OFF_BH 40960
#define OFF_BL 51200
#define STG 61440
#define SMEM3 (NSTAGE*STG)   // 184320

__device__ __forceinline__ void load_stage3(uint32_t sb,
        const __nv_bfloat16* Ah, const __nv_bfloat16* Al,
        const __nv_bfloat16* Bh, const __nv_bfloat16* Bl,
        int m0, int n0, int k0, int tid) {
    #pragma unroll
    for (int i = 0; i < 4; i++) {
        int q = tid + i*256;
        int r = q >> 2, c = q & 3;
        uint32_t d = sb + r*ASTR + c*16;
        size_t g = (size_t)(m0 + r) * C + k0 + c*8;
        CP_ASYNC16(d, Ah + g);
        CP_ASYNC16(d + OFF_AL, Al + g);
    }
    #pragma unroll
    for (int i = 0; i < 2; i++) {
        int q = tid + i*256;
        int r = q >> 2, c = q & 3;
        uint32_t d = sb + OFF_BH + r*ASTR + c*16;
        size_t g = (size_t)(n0 + r) * C + k0 + c*8;
        CP_ASYNC16(d, Bh + g);
        CP_ASYNC16(d + (OFF_BL - OFF_BH), Bl + g);
    }
}

__global__ __launch_bounds__(256, 1)
void tc_gemm3(const __nv_bfloat16* __restrict__ Ah, const __nv_bfloat16* __restrict__ Al,
              const __nv_bfloat16* __restrict__ Bh, const __nv_bfloat16* __restrict__ Bl,
              float* __restrict__ Y) {
    extern __shared__ char smc[];
    const uint32_t smb = smem_u32(smc);
    const int tid = threadIdx.x;
    const int lane = tid & 31, wid = tid >> 5;
    const int wm = wid & 3, wn = wid >> 2;        // 4x2 warps, warp tile 64x64
    const int n0 = blockIdx.x * GBN;
    const int m0 = blockIdx.y * GBM;

    float acc[4][8][4];
    #pragma unroll
    for (int a = 0; a < 4; a++)
        #pragma unroll
        for (int b = 0; b < 8; b++)
            #pragma unroll
            for (int c = 0; c < 4; c++) acc[a][b][c] = 0.f;

    const uint32_t aOff = (wm*64 + (lane & 15)) * ASTR + (lane >> 4) * 16;
    const uint32_t bOff = OFF_BH + (wn*64 + (lane & 7) + ((lane >> 4) & 1) * 8) * ASTR
                        + ((lane >> 3) & 1) * 16;

    load_stage3(smb, Ah, Al, Bh, Bl, m0, n0, 0, tid);
    CP_COMMIT();
    load_stage3(smb + STG, Ah, Al, Bh, Bl, m0, n0, GBK, tid);
    CP_COMMIT();

    int stg = 0;
    for (int ch = 0; ch < NCH; ch++) {
        if (ch < NCH - 1) { CP_WAIT(1); } else { CP_WAIT(0); }
        __syncthreads();
        if (ch + 2 < NCH) {
            int ps = stg + 2; if (ps >= NSTAGE) ps -= NSTAGE;
            load_stage3(smb + ps * STG, Ah, Al, Bh, Bl, m0, n0, (ch + 2) * GBK, tid);
            CP_COMMIT();
        }
        const uint32_t sb = smb + stg * STG;
        #pragma unroll
        for (int ks = 0; ks < 2; ks++) {
            uint32_t ah[4][4], al[4][4], bh[4][4], bl[4][4];
            #pragma unroll
            for (int mt = 0; mt < 4; mt++) {
                ldsm4(ah[mt], sb + aOff + mt * (16*ASTR) + ks * 32);
                ldsm4(al[mt], sb + OFF_AL + aOff + mt * (16*ASTR) + ks * 32);
            }
            #pragma unroll
            for (int np = 0; np < 4; np++) {
                ldsm4(bh[np], sb + bOff + np * (16*ASTR) + ks * 32);
                ldsm4(bl[np], sb + (OFF_BL - OFF_BH) + bOff + np * (16*ASTR) + ks * 32);
            }
            #pragma unroll
            for (int mt = 0; mt < 4; mt++)
                #pragma unroll
                for (int nt = 0; nt < 8; nt++)
                    hmma_bf16(acc[mt][nt], ah[mt], &bh[nt >> 1][(nt & 1) * 2]);
            #pragma unroll
            for (int mt = 0; mt < 4; mt++)
                #pragma unroll
                for (int nt = 0; nt < 8; nt++)
                    hmma_bf16(acc[mt][nt], ah[mt], &bl[nt >> 1][(nt & 1) * 2]);
            #pragma unroll
            for (int mt = 0; mt < 4; mt++)
                #pragma unroll
                for (int nt = 0; nt < 8; nt++)
                    hmma_bf16(acc[mt][nt], al[mt], &bh[nt >> 1][(nt & 1) * 2]);
        }
        stg++; if (stg == NSTAGE) stg = 0;
    }

    const int mrow = wm*64 + (lane >> 2);
    const int ncol = n0 + wn*64 + 2*(lane & 3);
    #pragma unroll
    for (int mt = 0; mt < 4; mt++)
        #pragma unroll
        for (int nt = 0; nt < 8; nt++) {
            int r = m0 + mrow + mt*16;
            int cq = ncol + nt*8;
            float2 v0 = make_float2(acc[mt][nt][0], acc[mt][nt][1]);
            float2 v1 = make_float2(acc[mt][nt][2], acc[mt][nt][3]);
            *(float2*)&Y[(size_t)r * 1024 + cq]       = v0;
            *(float2*)&Y[(size_t)(r + 8) * 1024 + cq] = v1;
        }
}

// ================= GEMM 1-term fp16: Y = A16 @ W16.T =================
// GBM=256, GBN=128, warp tile 64x64, same pipeline as gemm3.
#define OFF1_B  20480        // A: 256*80
#define STG1 30720           // 20480 + 128*80
#define SMEM1 (NSTAGE*STG1)  // 92160

__device__ __forceinline__ void load_stage1(uint32_t sb,
        const __half* Aw, const __half* Bw,
        int m0, int n0, int k0, int tid) {
    #pragma unroll
    for (int i = 0; i < 4; i++) {
        int q = tid + i*256;
        int r = q >> 2, c = q & 3;
        uint32_t d = sb + r*ASTR + c*16;
        size_t g = (size_t)(m0 + r) * C + k0 + c*8;
        CP_ASYNC16(d, Aw + g);
    }
    #pragma unroll
    for (int i = 0; i < 2; i++) {
        int q = tid + i*256;
        int r = q >> 2, c = q & 3;
        uint32_t d = sb + OFF1_B + r*ASTR + c*16;
        size_t g = (size_t)(n0 + r) * C + k0 + c*8;
        CP_ASYNC16(d, Bw + g);
    }
}

template<int MODE>
__global__ __launch_bounds__(256, 1)
void tc_gemm1(const __half* __restrict__ Aw, const __half* __restrict__ Bw,
              float* __restrict__ Y, const float* __restrict__ bias,
              const float* __restrict__ resid) {
    extern __shared__ char smc[];
    const uint32_t smb = smem_u32(smc);
    const int tid = threadIdx.x;
    const int lane = tid & 31, wid = tid >> 5;
    const int wm = wid & 3, wn = wid >> 2;        // 4x2 warps, warp tile 64x64
    const int n0 = blockIdx.x * GBN;
    const int m0 = blockIdx.y * GBM;
    const int bb = m0 / HW;
    const int p0 = m0 % HW;

    float acc[4][8][4];
    #pragma unroll
    for (int a = 0; a < 4; a++)
        #pragma unroll
        for (int b = 0; b < 8; b++)
            #pragma unroll
            for (int c = 0; c < 4; c++) acc[a][b][c] = 0.f;

    const uint32_t aOff = (wm*64 + (lane & 15)) * ASTR + (lane >> 4) * 16;
    const uint32_t bOff = OFF1_B + (wn*64 + (lane & 7) + ((lane >> 4) & 1) * 8) * ASTR
                        + ((lane >> 3) & 1) * 16;

    load_stage1(smb, Aw, Bw, m0, n0, 0, tid);
    CP_COMMIT();
    load_stage1(smb + STG1, Aw, Bw, m0, n0, GBK, tid);
    CP_COMMIT();

    int stg = 0;
    for (int ch = 0; ch < NCH; ch++) {
        if (ch < NCH - 1) { CP_WAIT(1); } else { CP_WAIT(0); }
        __syncthreads();
        if (ch + 2 < NCH) {
            int ps = stg + 2; if (ps >= NSTAGE) ps -= NSTAGE;
            load_stage1(smb + ps * STG1, Aw, Bw, m0, n0, (ch + 2) * GBK, tid);
            CP_COMMIT();
        }
        const uint32_t sb = smb + stg * STG1;
        #pragma unroll
        for (int ks = 0; ks < 2; ks++) {
            uint32_t ah[4][4], bh[4][4];
            #pragma unroll
            for (int mt = 0; mt < 4; mt++)
                ldsm4(ah[mt], sb + aOff + mt * (16*ASTR) + ks * 32);
            #pragma unroll
            for (int np = 0; np < 4; np++)
                ldsm4(bh[np], sb + bOff + np * (16*ASTR) + ks * 32);
            #pragma unroll
            for (int mt = 0; mt < 4; mt++)
                #pragma unroll
                for (int nt = 0; nt < 8; nt++)
                    hmma_f16(acc[mt][nt], ah[mt], &bh[nt >> 1][(nt & 1) * 2]);
        }
        stg++; if (stg == NSTAGE) stg = 0;
    }

    const int mrow = wm*64 + (lane >> 2);
    const int ncol = n0 + wn*64 + 2*(lane & 3);
    if (MODE == 0) {
        #pragma unroll
        for (int mt = 0; mt < 4; mt++)
            #pragma unroll
            for (int nt = 0; nt < 8; nt++) {
                int r = m0 + mrow + mt*16;
                int cq = ncol + nt*8;
                float2 v0 = make_float2(acc[mt][nt][0], acc[mt][nt][1]);
                float2 v1 = make_float2(acc[mt][nt][2], acc[mt][nt][3]);
                *(float2*)&Y[(size_t)r * C + cq]       = v0;
                *(float2*)&Y[(size_t)(r + 8) * C + cq] = v1;
            }
    } else {
        #pragma unroll
        for (int mt = 0; mt < 4; mt++)
            #pragma unroll
            for (int nt = 0; nt < 8; nt++) {
                int p = p0 + mrow + mt*16;
                int j = ncol + nt*8;
                float bj0 = bias[j], bj1 = bias[j + 1];
                size_t a00 = (size_t)bb*C*HW + (size_t)j*HW + p;
                Y[a00]          = acc[mt][nt][0] + bj0 + resid[a00];
                Y[a00 + HW]     = acc[mt][nt][1] + bj1 + resid[a00 + HW];
                Y[a00 + 8]      = acc[mt][nt][2] + bj0 + resid[a00 + 8];
                Y[a00 + HW + 8] = acc[mt][nt][3] + bj1 + resid[a00 + HW + 8];
            }
    }
}

// ---------------- dots: warp per (b,n); all 64 (i,j) pairs ----------------
__global__ void dots_kernel() {
    __shared__ float sQ[8][512];
    __shared__ float sK[8][512];
    int w = threadIdx.x >> 5, lane = threadIdx.x & 31;
    int m = blockIdx.x * 8 + w;                 // < 32768
    int b = m >> 12, n = m & 4095;
    const float4* q4 = (const float4*)(g_qk + (size_t)m * 1024);
    const float4* k4 = q4 + 128;                // K half of the row
    #pragma unroll
    for (int i = 0; i < 4; i++) {
        ((float4*)sQ[w])[lane + i*32] = q4[lane + i*32];
        ((float4*)sK[w])[lane + i*32] = k4[lane + i*32];
    }
    __syncwarp();
    #pragma unroll
    for (int t = 0; t < 2; t++) {
        int p = lane + t*32;                    // 0..63
        int i = p >> 3, j = p & 7;
        const float* qi = &sQ[w][i * HD];
        const float* kj = &sK[w][j * HD];
        float acc = 0.f;
        #pragma unroll
        for (int d = 0; d < HD; d++) acc += qi[d] * kj[d];
        g_att[(size_t)(b*64 + p) * HW + n] = acc * SCALE_ATT;
    }
}

// ---------------- softmax over n per (b,i,j) row, in place ----------------
__global__ void softmax_kernel() {
    float* row = g_att + (size_t)blockIdx.x * HW;
    __shared__ float sh[256];
    int tid = threadIdx.x;

    float mx = -1e30f;
    for (int n = tid; n < HW; n += 256) mx = fmaxf(mx, row[n]);
    sh[tid] = mx; __syncthreads();
    for (int off = 128; off > 0; off >>= 1) {
        if (tid < off) sh[tid] = fmaxf(sh[tid], sh[tid + off]);
        __syncthreads();
    }
    mx = sh[0]; __syncthreads();

    float sum = 0.f;
    for (int n = tid; n < HW; n += 256) sum += __expf(row[n] - mx);
    sh[tid] = sum; __syncthreads();
    for (int off = 128; off > 0; off >>= 1) {
        if (tid < off) sh[tid] += sh[tid + off];
        __syncthreads();
    }
    float inv = 1.f / sh[0];

    for (int n = tid; n < HW; n += 256) row[n] = __expf(row[n] - mx) * inv;
}

// ---------------- attv: ao[m, i*64+d] = sum_j att[b,i,j,n] * V[m, j*64+d]; fp16 ----------------
__global__ void attv_kernel() {
    size_t idx = (size_t)blockIdx.x * 256 + threadIdx.x;  // < M_TOT*C
    int m  = (int)(idx >> 9);
    int cc = (int)(idx & 511);
    int b = m >> 12, n = m & 4095;
    int i = cc >> 6, d = cc & 63;
    const float* att = g_att + ((size_t)(b*64 + i*8)) * HW + n;
    const float* v   = g_v + (size_t)m * C + d;
    float acc = 0.f;
    #pragma unroll
    for (int j = 0; j < NHEAD; j++)
        acc += att[(size_t)j * HW] * v[j * HD];
    g_ao_h[idx] = __float2half(acc);
}

// ---------------- launch ----------------
extern "C" void kernel_launch(void* const* d_in, const int* in_sizes, int n_in,
                              void* d_out, int out_size) {
    const float* x     = (const float*)d_in[0];
    const float* gamma = (const float*)d_in[1];
    const float* beta  = (const float*)d_in[2];
    const float* Wq    = (const float*)d_in[3];
    const float* Wk    = (const float*)d_in[4];
    const float* Wv    = (const float*)d_in[5];
    const float* Wp    = (const float*)d_in[6];
    const float* bp    = (const float*)d_in[7];
    float* out = (float*)d_out;

    float *p_xn, *p_qk, *p_v;
    __nv_bfloat16 *p_xah, *p_xal, *p_wh, *p_wl;
    __half *p_x16h, *p_w16, *p_aoh;
    cudaGetSymbolAddress((void**)&p_xn,   g_xn);
    cudaGetSymbolAddress((void**)&p_qk,   g_qk);
    cudaGetSymbolAddress((void**)&p_v,    g_v);
    cudaGetSymbolAddress((void**)&p_xah,  g_xa_hi);
    cudaGetSymbolAddress((void**)&p_xal,  g_xa_lo);
    cudaGetSymbolAddress((void**)&p_wh,   g_w_hi);
    cudaGetSymbolAddress((void**)&p_wl,   g_w_lo);
    cudaGetSymbolAddress((void**)&p_x16h, g_x16h);
    cudaGetSymbolAddress((void**)&p_w16,  g_w16);
    cudaGetSymbolAddress((void**)&p_aoh,  g_ao_h);

    cudaFuncSetAttribute(tc_gemm3,    cudaFuncAttributeMaxDynamicSharedMemorySize, SMEM3);
    cudaFuncSetAttribute(tc_gemm1<0>, cudaFuncAttributeMaxDynamicSharedMemorySize, SMEM1);
    cudaFuncSetAttribute(tc_gemm1<1>, cudaFuncAttributeMaxDynamicSharedMemorySize, SMEM1);

    gn_stats_kernel<<<B*NG, 512>>>(x);
    gn_split_kernel<<<dim3(HW/32, C/32, B), dim3(32, 8)>>>(x, gamma, beta);
    split_w_kernel<<<2*C*C/256, 256>>>(Wq, Wk, Wv, Wp);

    // fused Q|K GEMM: N = 1024, bf16 3-term (argmax-critical path)
    dim3 g3(1024/GBN, M_TOT/GBM);   // (8, 128)
    tc_gemm3<<<g3, 256, SMEM3>>>(p_xah, p_xal, p_wh, p_wl, p_qk);

    // V GEMM (fp16 1-term)
    dim3 g2(C/GBN, M_TOT/GBM);      // (4, 128)
    tc_gemm1<0><<<g2, 256, SMEM1>>>(p_x16h, p_w16, p_v, nullptr, nullptr);

    dots_kernel<<<M_TOT/8, 256>>>();
    softmax_kernel<<<B*NHEAD*NHEAD, 256>>>();
    attv_kernel<<<(unsigned)(M_TOT*(size_t)C/256), 256>>>();

    // proj GEMM (fp16 1-term) + bias + residual
    tc_gemm1<1><<<g2, 256, SMEM1>>>(p_aoh, p_w16 + (size_t)C*C, out, bp, p_xn);
}

// round 14
// speedup vs baseline: 1.3741x; 1.0361x over previous
#include <cuda_runtime.h>
#include <cuda_bf16.h>
#include <cuda_fp16.h>
#include <cstdint>
#include <cstddef>

#define B 8
#define C 512
#define HW 4096
#define M_TOT (B*HW)          // 32768
#define NG 32
#define CPG (C/NG)            // 16
#define GRP_ELEMS (CPG*HW)    // 65536
#define NHEAD 8
#define HD 64
#define EPS_GN 1e-6f
#define SCALE_ATT 8.0f        // sqrt(64), reference MULTIPLIES

// ---------------- scratch ----------------
__device__ float g_xn [B*C*HW];                 // normalized x, (b,c,p) fp32 (residual)
__device__ float g_qk [(size_t)M_TOT*1024];     // [Q | K] row-major, stride 1024
__device__ float g_v  [M_TOT*C];
__device__ float g_att[B*NHEAD*NHEAD*HW];       // dots then att, (b,i,j,n)
__device__ __nv_bfloat16 g_xa_hi[M_TOT*C];      // xn row-major (m,k) bf16 split (QK path)
__device__ __nv_bfloat16 g_xa_lo[M_TOT*C];
__device__ __half g_x16h[M_TOT*C];              // xn row-major fp16 (V path)
__device__ __nv_bfloat16 g_w_hi[2*C*C];         // [Wq;Wk] bf16 split (j,k)
__device__ __nv_bfloat16 g_w_lo[2*C*C];
__device__ __half g_w16[2*C*C];                 // [Wv;Wp] fp16 (j,k)
__device__ __half g_ao_h[M_TOT*C];              // attention out fp16 (m,c)
__device__ float g_mean[B*NG];
__device__ float g_rstd[B*NG];

// ---------------- helpers ----------------
__device__ __forceinline__ uint32_t smem_u32(const void* p) {
    uint32_t a;
    asm("{ .reg .u64 t; cvta.to.shared.u64 t, %1; cvt.u32.u64 %0, t; }" : "=r"(a) : "l"(p));
    return a;
}
#define CP_ASYNC16(s, g)  asm volatile("cp.async.cg.shared.global [%0], [%1], 16;" :: "r"(s), "l"(g))
#define CP_COMMIT()       asm volatile("cp.async.commit_group;" ::: "memory")
#define CP_WAIT(n)        asm volatile("cp.async.wait_group %0;" :: "n"(n) : "memory")

__device__ __forceinline__ void ldsm4(uint32_t* r, uint32_t addr) {
    asm volatile("ldmatrix.sync.aligned.m8n8.x4.shared.b16 {%0,%1,%2,%3}, [%4];"
        : "=r"(r[0]), "=r"(r[1]), "=r"(r[2]), "=r"(r[3]) : "r"(addr));
}
__device__ __forceinline__ void hmma_bf16(float* c, const uint32_t* a, const uint32_t* b) {
    asm volatile("mma.sync.aligned.m16n8k16.row.col.f32.bf16.bf16.f32 "
        "{%0,%1,%2,%3}, {%4,%5,%6,%7}, {%8,%9}, {%0,%1,%2,%3};"
        : "+f"(c[0]), "+f"(c[1]), "+f"(c[2]), "+f"(c[3])
        : "r"(a[0]), "r"(a[1]), "r"(a[2]), "r"(a[3]), "r"(b[0]), "r"(b[1]));
}
__device__ __forceinline__ void hmma_f16(float* c, const uint32_t* a, const uint32_t* b) {
    asm volatile("mma.sync.aligned.m16n8k16.row.col.f32.f16.f16.f32 "
        "{%0,%1,%2,%3}, {%4,%5,%6,%7}, {%8,%9}, {%0,%1,%2,%3};"
        : "+f"(c[0]), "+f"(c[1]), "+f"(c[2]), "+f"(c[3])
        : "r"(a[0]), "r"(a[1]), "r"(a[2]), "r"(a[3]), "r"(b[0]), "r"(b[1]));
}

// ---------------- GroupNorm: stats ----------------
__global__ void gn_stats_kernel(const float* __restrict__ x) {
    int grp = blockIdx.x;
    const float* p = x + (size_t)grp * GRP_ELEMS;
    float s = 0.f, s2 = 0.f;
    for (int i = threadIdx.x; i < GRP_ELEMS; i += blockDim.x) {
        float v = p[i]; s += v; s2 += v * v;
    }
    __shared__ float sh[512], sh2[512];
    sh[threadIdx.x] = s; sh2[threadIdx.x] = s2;
    __syncthreads();
    for (int off = blockDim.x >> 1; off > 0; off >>= 1) {
        if (threadIdx.x < off) {
            sh[threadIdx.x]  += sh[threadIdx.x + off];
            sh2[threadIdx.x] += sh2[threadIdx.x + off];
        }
        __syncthreads();
    }
    if (threadIdx.x == 0) {
        float mean = sh[0] * (1.0f / GRP_ELEMS);
        float var  = sh2[0] * (1.0f / GRP_ELEMS) - mean * mean;
        g_mean[grp] = mean;
        g_rstd[grp] = rsqrtf(var + EPS_GN);
    }
}

// ---------------- fused GroupNorm-apply + transpose + splits ----------------
__global__ void gn_split_kernel(const float* __restrict__ x,
                                const float* __restrict__ gamma,
                                const float* __restrict__ beta) {
    __shared__ float sm[32][33];
    int p0 = blockIdx.x * 32, c0 = blockIdx.y * 32, b = blockIdx.z;
    int tx = threadIdx.x, ty = threadIdx.y;     // (32, 8)
    #pragma unroll
    for (int i = 0; i < 4; i++) {
        int c = c0 + ty + i*8;
        int grp = b*NG + (c >> 4);
        float m = g_mean[grp], r = g_rstd[grp];
        float ga = gamma[c], be = beta[c];
        size_t o = (size_t)b*C*HW + (size_t)c*HW + p0 + tx;
        float v = (x[o] - m) * r * ga + be;
        g_xn[o] = v;
        sm[ty + i*8][tx] = v;
    }
    __syncthreads();
    #pragma unroll
    for (int i = 0; i < 4; i++) {
        int p = p0 + ty + i*8;
        float v = sm[tx][ty + i*8];
        size_t o = (size_t)(b*HW + p) * C + c0 + tx;
        __nv_bfloat16 h = __float2bfloat16(v);
        g_xa_hi[o] = h;
        g_xa_lo[o] = __float2bfloat16(v - __bfloat162float(h));
        g_x16h[o] = __float2half(v);
    }
}

// ---------------- split weights ----------------
__global__ void split_w_kernel(const float* __restrict__ Wq, const float* __restrict__ Wk,
                               const float* __restrict__ Wv, const float* __restrict__ Wp) {
    int idx = blockIdx.x * 256 + threadIdx.x;   // < 2*C*C
    int wsel = idx >> 18;
    int off  = idx & (C*C - 1);
    float vqk = (wsel == 0) ? Wq[off] : Wk[off];
    __nv_bfloat16 h = __float2bfloat16(vqk);
    g_w_hi[idx] = h;
    g_w_lo[idx] = __float2bfloat16(vqk - __bfloat162float(h));
    float vvp = (wsel == 0) ? Wv[off] : Wp[off];
    g_w16[idx] = __float2half(vvp);
}

// ================= GEMM 3-term bf16 (QK fused): Y[m, 0..1023] =================
#define GBM 256
#define GBN 128
#define GBK 32
#define NCH (C/GBK)          // 16
#define NSTAGE 3
#define ASTR 80
#define OFF_AL 20480         // 256*80
#define OFF_BH 40960
#define OFF_BL 51200
#define STG 61440
#define SMEM3 (NSTAGE*STG)   // 184320

__device__ __forceinline__ void load_stage3(uint32_t sb,
        const __nv_bfloat16* Ah, const __nv_bfloat16* Al,
        const __nv_bfloat16* Bh, const __nv_bfloat16* Bl,
        int m0, int n0, int k0, int tid) {
    #pragma unroll
    for (int i = 0; i < 4; i++) {
        int q = tid + i*256;
        int r = q >> 2, c = q & 3;
        uint32_t d = sb + r*ASTR + c*16;
        size_t g = (size_t)(m0 + r) * C + k0 + c*8;
        CP_ASYNC16(d, Ah + g);
        CP_ASYNC16(d + OFF_AL, Al + g);
    }
    #pragma unroll
    for (int i = 0; i < 2; i++) {
        int q = tid + i*256;
        int r = q >> 2, c = q & 3;
        uint32_t d = sb + OFF_BH + r*ASTR + c*16;
        size_t g = (size_t)(n0 + r) * C + k0 + c*8;
        CP_ASYNC16(d, Bh + g);
        CP_ASYNC16(d + (OFF_BL - OFF_BH), Bl + g);
    }
}

__global__ __launch_bounds__(256, 1)
void tc_gemm3(const __nv_bfloat16* __restrict__ Ah, const __nv_bfloat16* __restrict__ Al,
              const __nv_bfloat16* __restrict__ Bh, const __nv_bfloat16* __restrict__ Bl,
              float* __restrict__ Y) {
    extern __shared__ char smc[];
    const uint32_t smb = smem_u32(smc);
    const int tid = threadIdx.x;
    const int lane = tid & 31, wid = tid >> 5;
    const int wm = wid & 3, wn = wid >> 2;        // 4x2 warps, warp tile 64x64
    const int n0 = blockIdx.x * GBN;
    const int m0 = blockIdx.y * GBM;

    float acc[4][8][4];
    #pragma unroll
    for (int a = 0; a < 4; a++)
        #pragma unroll
        for (int b = 0; b < 8; b++)
            #pragma unroll
            for (int c = 0; c < 4; c++) acc[a][b][c] = 0.f;

    const uint32_t aOff = (wm*64 + (lane & 15)) * ASTR + (lane >> 4) * 16;
    const uint32_t bOff = OFF_BH + (wn*64 + (lane & 7) + ((lane >> 4) & 1) * 8) * ASTR
                        + ((lane >> 3) & 1) * 16;

    load_stage3(smb, Ah, Al, Bh, Bl, m0, n0, 0, tid);
    CP_COMMIT();
    load_stage3(smb + STG, Ah, Al, Bh, Bl, m0, n0, GBK, tid);
    CP_COMMIT();

    int stg = 0;
    for (int ch = 0; ch < NCH; ch++) {
        if (ch < NCH - 1) { CP_WAIT(1); } else { CP_WAIT(0); }
        __syncthreads();
        if (ch + 2 < NCH) {
            int ps = stg + 2; if (ps >= NSTAGE) ps -= NSTAGE;
            load_stage3(smb + ps * STG, Ah, Al, Bh, Bl, m0, n0, (ch + 2) * GBK, tid);
            CP_COMMIT();
        }
        const uint32_t sb = smb + stg * STG;
        #pragma unroll
        for (int ks = 0; ks < 2; ks++) {
            uint32_t ah[4][4], al[4][4], bh[4][4], bl[4][4];
            #pragma unroll
            for (int mt = 0; mt < 4; mt++) {
                ldsm4(ah[mt], sb + aOff + mt * (16*ASTR) + ks * 32);
                ldsm4(al[mt], sb + OFF_AL + aOff + mt * (16*ASTR) + ks * 32);
            }
            #pragma unroll
            for (int np = 0; np < 4; np++) {
                ldsm4(bh[np], sb + bOff + np * (16*ASTR) + ks * 32);
                ldsm4(bl[np], sb + (OFF_BL - OFF_BH) + bOff + np * (16*ASTR) + ks * 32);
            }
            #pragma unroll
            for (int mt = 0; mt < 4; mt++)
                #pragma unroll
                for (int nt = 0; nt < 8; nt++)
                    hmma_bf16(acc[mt][nt], ah[mt], &bh[nt >> 1][(nt & 1) * 2]);
            #pragma unroll
            for (int mt = 0; mt < 4; mt++)
                #pragma unroll
                for (int nt = 0; nt < 8; nt++)
                    hmma_bf16(acc[mt][nt], ah[mt], &bl[nt >> 1][(nt & 1) * 2]);
            #pragma unroll
            for (int mt = 0; mt < 4; mt++)
                #pragma unroll
                for (int nt = 0; nt < 8; nt++)
                    hmma_bf16(acc[mt][nt], al[mt], &bh[nt >> 1][(nt & 1) * 2]);
        }
        stg++; if (stg == NSTAGE) stg = 0;
    }

    const int mrow = wm*64 + (lane >> 2);
    const int ncol = n0 + wn*64 + 2*(lane & 3);
    #pragma unroll
    for (int mt = 0; mt < 4; mt++)
        #pragma unroll
        for (int nt = 0; nt < 8; nt++) {
            int r = m0 + mrow + mt*16;
            int cq = ncol + nt*8;
            float2 v0 = make_float2(acc[mt][nt][0], acc[mt][nt][1]);
            float2 v1 = make_float2(acc[mt][nt][2], acc[mt][nt][3]);
            *(float2*)&Y[(size_t)r * 1024 + cq]       = v0;
            *(float2*)&Y[(size_t)(r + 8) * 1024 + cq] = v1;
        }
}

// ================= GEMM 1-term fp16, GBK=64: Y = A16 @ W16.T =================
// GBM=256, GBN=128, warp tile 64x64; row stride 144 B (9x16B, conflict-free).
#define GBK1 64
#define NCH1 (C/GBK1)        // 8
#define ASTR1 144
#define OFF1_B 36864         // 256*144
#define STG1 55296           // + 128*144
#define SMEM1 (NSTAGE*STG1)  // 165888

__device__ __forceinline__ void load_stage1(uint32_t sb,
        const __half* Aw, const __half* Bw,
        int m0, int n0, int k0, int tid) {
    #pragma unroll
    for (int i = 0; i < 8; i++) {
        int q = tid + i*256;
        int r = q >> 3, c = q & 7;
        uint32_t d = sb + r*ASTR1 + c*16;
        size_t g = (size_t)(m0 + r) * C + k0 + c*8;
        CP_ASYNC16(d, Aw + g);
    }
    #pragma unroll
    for (int i = 0; i < 4; i++) {
        int q = tid + i*256;
        int r = q >> 3, c = q & 7;
        uint32_t d = sb + OFF1_B + r*ASTR1 + c*16;
        size_t g = (size_t)(n0 + r) * C + k0 + c*8;
        CP_ASYNC16(d, Bw + g);
    }
}

template<int MODE>
__global__ __launch_bounds__(256, 1)
void tc_gemm1(const __half* __restrict__ Aw, const __half* __restrict__ Bw,
              float* __restrict__ Y, const float* __restrict__ bias,
              const float* __restrict__ resid) {
    extern __shared__ char smc[];
    const uint32_t smb = smem_u32(smc);
    const int tid = threadIdx.x;
    const int lane = tid & 31, wid = tid >> 5;
    const int wm = wid & 3, wn = wid >> 2;        // 4x2 warps, warp tile 64x64
    const int n0 = blockIdx.x * GBN;
    const int m0 = blockIdx.y * GBM;
    const int bb = m0 / HW;
    const int p0 = m0 % HW;

    float acc[4][8][4];
    #pragma unroll
    for (int a = 0; a < 4; a++)
        #pragma unroll
        for (int b = 0; b < 8; b++)
            #pragma unroll
            for (int c = 0; c < 4; c++) acc[a][b][c] = 0.f;

    const uint32_t aOff = (wm*64 + (lane & 15)) * ASTR1 + (lane >> 4) * 16;
    const uint32_t bOff = OFF1_B + (wn*64 + (lane & 7) + ((lane >> 4) & 1) * 8) * ASTR1
                        + ((lane >> 3) & 1) * 16;

    load_stage1(smb, Aw, Bw, m0, n0, 0, tid);
    CP_COMMIT();
    load_stage1(smb + STG1, Aw, Bw, m0, n0, GBK1, tid);
    CP_COMMIT();

    int stg = 0;
    for (int ch = 0; ch < NCH1; ch++) {
        if (ch < NCH1 - 1) { CP_WAIT(1); } else { CP_WAIT(0); }
        __syncthreads();
        if (ch + 2 < NCH1) {
            int ps = stg + 2; if (ps >= NSTAGE) ps -= NSTAGE;
            load_stage1(smb + ps * STG1, Aw, Bw, m0, n0, (ch + 2) * GBK1, tid);
            CP_COMMIT();
        }
        const uint32_t sb = smb + stg * STG1;
        #pragma unroll
        for (int ks = 0; ks < 4; ks++) {
            uint32_t ah[4][4], bh[4][4];
            #pragma unroll
            for (int mt = 0; mt < 4; mt++)
                ldsm4(ah[mt], sb + aOff + mt * (16*ASTR1) + ks * 32);
            #pragma unroll
            for (int np = 0; np < 4; np++)
                ldsm4(bh[np], sb + bOff + np * (16*ASTR1) + ks * 32);
            #pragma unroll
            for (int mt = 0; mt < 4; mt++)
                #pragma unroll
                for (int nt = 0; nt < 8; nt++)
                    hmma_f16(acc[mt][nt], ah[mt], &bh[nt >> 1][(nt & 1) * 2]);
        }
        stg++; if (stg == NSTAGE) stg = 0;
    }

    const int mrow = wm*64 + (lane >> 2);
    const int ncol = n0 + wn*64 + 2*(lane & 3);
    if (MODE == 0) {
        #pragma unroll
        for (int mt = 0; mt < 4; mt++)
            #pragma unroll
            for (int nt = 0; nt < 8; nt++) {
                int r = m0 + mrow + mt*16;
                int cq = ncol + nt*8;
                float2 v0 = make_float2(acc[mt][nt][0], acc[mt][nt][1]);
                float2 v1 = make_float2(acc[mt][nt][2], acc[mt][nt][3]);
                *(float2*)&Y[(size_t)r * C + cq]       = v0;
                *(float2*)&Y[(size_t)(r + 8) * C + cq] = v1;
            }
    } else {
        #pragma unroll
        for (int mt = 0; mt < 4; mt++)
            #pragma unroll
            for (int nt = 0; nt < 8; nt++) {
                int p = p0 + mrow + mt*16;
                int j = ncol + nt*8;
                float bj0 = bias[j], bj1 = bias[j + 1];
                size_t a00 = (size_t)bb*C*HW + (size_t)j*HW + p;
                Y[a00]          = acc[mt][nt][0] + bj0 + resid[a00];
                Y[a00 + HW]     = acc[mt][nt][1] + bj1 + resid[a00 + HW];
                Y[a00 + 8]      = acc[mt][nt][2] + bj0 + resid[a00 + 8];
                Y[a00 + HW + 8] = acc[mt][nt][3] + bj1 + resid[a00 + HW + 8];
            }
    }
}

// ---------------- dots: warp per (b,n); all 64 (i,j) pairs ----------------
__global__ void dots_kernel() {
    __shared__ float sQ[8][512];
    __shared__ float sK[8][512];
    int w = threadIdx.x >> 5, lane = threadIdx.x & 31;
    int m = blockIdx.x * 8 + w;                 // < 32768
    int b = m >> 12, n = m & 4095;
    const float4* q4 = (const float4*)(g_qk + (size_t)m * 1024);
    const float4* k4 = q4 + 128;                // K half of the row
    #pragma unroll
    for (int i = 0; i < 4; i++) {
        ((float4*)sQ[w])[lane + i*32] = q4[lane + i*32];
        ((float4*)sK[w])[lane + i*32] = k4[lane + i*32];
    }
    __syncwarp();
    #pragma unroll
    for (int t = 0; t < 2; t++) {
        int p = lane + t*32;                    // 0..63
        int i = p >> 3, j = p & 7;
        const float* qi = &sQ[w][i * HD];
        const float* kj = &sK[w][j * HD];
        float acc = 0.f;
        #pragma unroll
        for (int d = 0; d < HD; d++) acc += qi[d] * kj[d];
        g_att[(size_t)(b*64 + p) * HW + n] = acc * SCALE_ATT;
    }
}

// ---------------- softmax over n per (b,i,j) row, in place ----------------
__global__ void softmax_kernel() {
    float* row = g_att + (size_t)blockIdx.x * HW;
    __shared__ float sh[256];
    int tid = threadIdx.x;

    float mx = -1e30f;
    for (int n = tid; n < HW; n += 256) mx = fmaxf(mx, row[n]);
    sh[tid] = mx; __syncthreads();
    for (int off = 128; off > 0; off >>= 1) {
        if (tid < off) sh[tid] = fmaxf(sh[tid], sh[tid + off]);
        __syncthreads();
    }
    mx = sh[0]; __syncthreads();

    float sum = 0.f;
    for (int n = tid; n < HW; n += 256) sum += __expf(row[n] - mx);
    sh[tid] = sum; __syncthreads();
    for (int off = 128; off > 0; off >>= 1) {
        if (tid < off) sh[tid] += sh[tid + off];
        __syncthreads();
    }
    float inv = 1.f / sh[0];

    for (int n = tid; n < HW; n += 256) row[n] = __expf(row[n] - mx) * inv;
}

// ---------------- attv: ao[m, i*64+d] = sum_j att[b,i,j,n] * V[m, j*64+d]; fp16 ----------------
__global__ void attv_kernel() {
    size_t idx = (size_t)blockIdx.x * 256 + threadIdx.x;  // < M_TOT*C
    int m  = (int)(idx >> 9);
    int cc = (int)(idx & 511);
    int b = m >> 12, n = m & 4095;
    int i = cc >> 6, d = cc & 63;
    const float* att = g_att + ((size_t)(b*64 + i*8)) * HW + n;
    const float* v   = g_v + (size_t)m * C + d;
    float acc = 0.f;
    #pragma unroll
    for (int j = 0; j < NHEAD; j++)
        acc += att[(size_t)j * HW] * v[j * HD];
    g_ao_h[idx] = __float2half(acc);
}

// ---------------- launch ----------------
extern "C" void kernel_launch(void* const* d_in, const int* in_sizes, int n_in,
                              void* d_out, int out_size) {
    const float* x     = (const float*)d_in[0];
    const float* gamma = (const float*)d_in[1];
    const float* beta  = (const float*)d_in[2];
    const float* Wq    = (const float*)d_in[3];
    const float* Wk    = (const float*)d_in[4];
    const float* Wv    = (const float*)d_in[5];
    const float* Wp    = (const float*)d_in[6];
    const float* bp    = (const float*)d_in[7];
    float* out = (float*)d_out;

    float *p_xn, *p_qk, *p_v;
    __nv_bfloat16 *p_xah, *p_xal, *p_wh, *p_wl;
    __half *p_x16h, *p_w16, *p_aoh;
    cudaGetSymbolAddress((void**)&p_xn,   g_xn);
    cudaGetSymbolAddress((void**)&p_qk,   g_qk);
    cudaGetSymbolAddress((void**)&p_v,    g_v);
    cudaGetSymbolAddress((void**)&p_xah,  g_xa_hi);
    cudaGetSymbolAddress((void**)&p_xal,  g_xa_lo);
    cudaGetSymbolAddress((void**)&p_wh,   g_w_hi);
    cudaGetSymbolAddress((void**)&p_wl,   g_w_lo);
    cudaGetSymbolAddress((void**)&p_x16h, g_x16h);
    cudaGetSymbolAddress((void**)&p_w16,  g_w16);
    cudaGetSymbolAddress((void**)&p_aoh,  g_ao_h);

    cudaFuncSetAttribute(tc_gemm3,    cudaFuncAttributeMaxDynamicSharedMemorySize, SMEM3);
    cudaFuncSetAttribute(tc_gemm1<0>, cudaFuncAttributeMaxDynamicSharedMemorySize, SMEM1);
    cudaFuncSetAttribute(tc_gemm1<1>, cudaFuncAttributeMaxDynamicSharedMemorySize, SMEM1);

    // one-time side stream + events (created on the uncaptured correctness call)
    static cudaStream_t s2 = nullptr;
    static cudaEvent_t evFork = nullptr, evV = nullptr;
    if (s2 == nullptr) {
        cudaStreamCreateWithFlags(&s2, cudaStreamNonBlocking);
        cudaEventCreateWithFlags(&evFork, cudaEventDisableTiming);
        cudaEventCreateWithFlags(&evV, cudaEventDisableTiming);
    }

    gn_stats_kernel<<<B*NG, 512>>>(x);
    gn_split_kernel<<<dim3(HW/32, C/32, B), dim3(32, 8)>>>(x, gamma, beta);
    split_w_kernel<<<2*C*C/256, 256>>>(Wq, Wk, Wv, Wp);

    // fork: V GEMM (depends only on gn_split/split_w) on side stream
    cudaEventRecord(evFork, 0);
    cudaStreamWaitEvent(s2, evFork, 0);
    dim3 g2(C/GBN, M_TOT/GBM);      // (4, 128)
    tc_gemm1<0><<<g2, 256, SMEM1, s2>>>(p_x16h, p_w16, p_v, nullptr, nullptr);
    cudaEventRecord(evV, s2);

    // main stream: QK GEMM -> dots -> softmax
    dim3 g3(1024/GBN, M_TOT/GBM);   // (8, 128)
    tc_gemm3<<<g3, 256, SMEM3>>>(p_xah, p_xal, p_wh, p_wl, p_qk);
    dots_kernel<<<M_TOT/8, 256>>>();
    softmax_kernel<<<B*NHEAD*NHEAD, 256>>>();

    // join: attv needs both softmax (stream 0) and V (s2)
    cudaStreamWaitEvent(0, evV, 0);
    attv_kernel<<<(unsigned)(M_TOT*(size_t)C/256), 256>>>();

    // proj GEMM (fp16 1-term) + bias + residual
    tc_gemm1<1><<<g2, 256, SMEM1>>>(p_aoh, p_w16 + (size_t)C*C, out, bp, p_xn);
}

// round 15
// speedup vs baseline: 1.3880x; 1.0101x over previous
#include <cuda_runtime.h>
#include <cuda_bf16.h>
#include <cuda_fp16.h>
#include <cstdint>
#include <cstddef>

#define B 8
#define C 512
#define HW 4096
#define M_TOT (B*HW)          // 32768
#define NG 32
#define CPG (C/NG)            // 16
#define GRP_ELEMS (CPG*HW)    // 65536
#define NHEAD 8
#define HD 64
#define EPS_GN 1e-6f
#define SCALE_ATT 8.0f        // sqrt(64), reference MULTIPLIES

// ---------------- scratch ----------------
__device__ float g_xn [B*C*HW];                 // normalized x, (b,c,p) fp32 (residual)
__device__ float g_qk [(size_t)M_TOT*1024];     // [Q | K] row-major, stride 1024
__device__ float g_v  [M_TOT*C];
__device__ float g_att[B*NHEAD*NHEAD*HW];       // dots then att, (b,i,j,n)
__device__ __nv_bfloat16 g_xa_hi[M_TOT*C];      // xn row-major (m,k) bf16 split (QK path)
__device__ __nv_bfloat16 g_xa_lo[M_TOT*C];
__device__ __half g_x16h[M_TOT*C];              // xn row-major fp16 (V path)
__device__ __nv_bfloat16 g_w_hi[2*C*C];         // [Wq;Wk] bf16 split (j,k)
__device__ __nv_bfloat16 g_w_lo[2*C*C];
__device__ __half g_w16[2*C*C];                 // [Wv;Wp] fp16 (j,k)
__device__ __half g_ao_h[M_TOT*C];              // attention out fp16 (m,c)
__device__ float g_mean[B*NG];
__device__ float g_rstd[B*NG];

// ---------------- helpers ----------------
__device__ __forceinline__ uint32_t smem_u32(const void* p) {
    uint32_t a;
    asm("{ .reg .u64 t; cvta.to.shared.u64 t, %1; cvt.u32.u64 %0, t; }" : "=r"(a) : "l"(p));
    return a;
}
#define CP_ASYNC16(s, g)  asm volatile("cp.async.cg.shared.global [%0], [%1], 16;" :: "r"(s), "l"(g))
#define CP_COMMIT()       asm volatile("cp.async.commit_group;" ::: "memory")
#define CP_WAIT(n)        asm volatile("cp.async.wait_group %0;" :: "n"(n) : "memory")

__device__ __forceinline__ void ldsm4(uint32_t* r, uint32_t addr) {
    asm volatile("ldmatrix.sync.aligned.m8n8.x4.shared.b16 {%0,%1,%2,%3}, [%4];"
        : "=r"(r[0]), "=r"(r[1]), "=r"(r[2]), "=r"(r[3]) : "r"(addr));
}
__device__ __forceinline__ void hmma_bf16(float* c, const uint32_t* a, const uint32_t* b) {
    asm volatile("mma.sync.aligned.m16n8k16.row.col.f32.bf16.bf16.f32 "
        "{%0,%1,%2,%3}, {%4,%5,%6,%7}, {%8,%9}, {%0,%1,%2,%3};"
        : "+f"(c[0]), "+f"(c[1]), "+f"(c[2]), "+f"(c[3])
        : "r"(a[0]), "r"(a[1]), "r"(a[2]), "r"(a[3]), "r"(b[0]), "r"(b[1]));
}
__device__ __forceinline__ void hmma_f16(float* c, const uint32_t* a, const uint32_t* b) {
    asm volatile("mma.sync.aligned.m16n8k16.row.col.f32.f16.f16.f32 "
        "{%0,%1,%2,%3}, {%4,%5,%6,%7}, {%8,%9}, {%0,%1,%2,%3};"
        : "+f"(c[0]), "+f"(c[1]), "+f"(c[2]), "+f"(c[3])
        : "r"(a[0]), "r"(a[1]), "r"(a[2]), "r"(a[3]), "r"(b[0]), "r"(b[1]));
}

// ---------------- GroupNorm: stats ----------------
__global__ void gn_stats_kernel(const float* __restrict__ x) {
    int grp = blockIdx.x;
    const float* p = x + (size_t)grp * GRP_ELEMS;
    float s = 0.f, s2 = 0.f;
    for (int i = threadIdx.x; i < GRP_ELEMS; i += blockDim.x) {
        float v = p[i]; s += v; s2 += v * v;
    }
    __shared__ float sh[512], sh2[512];
    sh[threadIdx.x] = s; sh2[threadIdx.x] = s2;
    __syncthreads();
    for (int off = blockDim.x >> 1; off > 0; off >>= 1) {
        if (threadIdx.x < off) {
            sh[threadIdx.x]  += sh[threadIdx.x + off];
            sh2[threadIdx.x] += sh2[threadIdx.x + off];
        }
        __syncthreads();
    }
    if (threadIdx.x == 0) {
        float mean = sh[0] * (1.0f / GRP_ELEMS);
        float var  = sh2[0] * (1.0f / GRP_ELEMS) - mean * mean;
        g_mean[grp] = mean;
        g_rstd[grp] = rsqrtf(var + EPS_GN);
    }
}

// ---------------- fused GroupNorm-apply + transpose + splits ----------------
__global__ void gn_split_kernel(const float* __restrict__ x,
                                const float* __restrict__ gamma,
                                const float* __restrict__ beta) {
    __shared__ float sm[32][33];
    int p0 = blockIdx.x * 32, c0 = blockIdx.y * 32, b = blockIdx.z;
    int tx = threadIdx.x, ty = threadIdx.y;     // (32, 8)
    #pragma unroll
    for (int i = 0; i < 4; i++) {
        int c = c0 + ty + i*8;
        int grp = b*NG + (c >> 4);
        float m = g_mean[grp], r = g_rstd[grp];
        float ga = gamma[c], be = beta[c];
        size_t o = (size_t)b*C*HW + (size_t)c*HW + p0 + tx;
        float v = (x[o] - m) * r * ga + be;
        g_xn[o] = v;
        sm[ty + i*8][tx] = v;
    }
    __syncthreads();
    #pragma unroll
    for (int i = 0; i < 4; i++) {
        int p = p0 + ty + i*8;
        float v = sm[tx][ty + i*8];
        size_t o = (size_t)(b*HW + p) * C + c0 + tx;
        __nv_bfloat16 h = __float2bfloat16(v);
        g_xa_hi[o] = h;
        g_xa_lo[o] = __float2bfloat16(v - __bfloat162float(h));
        g_x16h[o] = __float2half(v);
    }
}

// ---------------- split weights ----------------
__global__ void split_w_kernel(const float* __restrict__ Wq, const float* __restrict__ Wk,
                               const float* __restrict__ Wv, const float* __restrict__ Wp) {
    int idx = blockIdx.x * 256 + threadIdx.x;   // < 2*C*C
    int wsel = idx >> 18;
    int off  = idx & (C*C - 1);
    float vqk = (wsel == 0) ? Wq[off] : Wk[off];
    __nv_bfloat16 h = __float2bfloat16(vqk);
    g_w_hi[idx] = h;
    g_w_lo[idx] = __float2bfloat16(vqk - __bfloat162float(h));
    float vvp = (wsel == 0) ? Wv[off] : Wp[off];
    g_w16[idx] = __float2half(vvp);
}

// ================= GEMM 3-term bf16 (QK fused), GBK=64, 2-stage =================
// GBM=256, GBN=128, warp tile 64x64; row stride 144 B (9x16B, ldsm conflict-free).
#define GBM 256
#define GBN 128
#define GBK3 64
#define NCH3 (C/GBK3)        // 8
#define ASTR3 144
#define OFF3_AL 36864        // 256*144
#define OFF3_BH 73728
#define OFF3_BL 92160        // + 128*144
#define STG3 110592          // (256+256+128+128)*144
#define SMEM3 (2*STG3)       // 221184

__device__ __forceinline__ void load_stage3(uint32_t sb,
        const __nv_bfloat16* Ah, const __nv_bfloat16* Al,
        const __nv_bfloat16* Bh, const __nv_bfloat16* Bl,
        int m0, int n0, int k0, int tid) {
    #pragma unroll
    for (int i = 0; i < 8; i++) {
        int q = tid + i*256;
        int r = q >> 3, c = q & 7;
        uint32_t d = sb + r*ASTR3 + c*16;
        size_t g = (size_t)(m0 + r) * C + k0 + c*8;
        CP_ASYNC16(d, Ah + g);
        CP_ASYNC16(d + OFF3_AL, Al + g);
    }
    #pragma unroll
    for (int i = 0; i < 4; i++) {
        int q = tid + i*256;
        int r = q >> 3, c = q & 7;
        uint32_t d = sb + OFF3_BH + r*ASTR3 + c*16;
        size_t g = (size_t)(n0 + r) * C + k0 + c*8;
        CP_ASYNC16(d, Bh + g);
        CP_ASYNC16(d + (OFF3_BL - OFF3_BH), Bl + g);
    }
}

__global__ __launch_bounds__(256, 1)
void tc_gemm3(const __nv_bfloat16* __restrict__ Ah, const __nv_bfloat16* __restrict__ Al,
              const __nv_bfloat16* __restrict__ Bh, const __nv_bfloat16* __restrict__ Bl,
              float* __restrict__ Y) {
    extern __shared__ char smc[];
    const uint32_t smb = smem_u32(smc);
    const int tid = threadIdx.x;
    const int lane = tid & 31, wid = tid >> 5;
    const int wm = wid & 3, wn = wid >> 2;        // 4x2 warps, warp tile 64x64
    const int n0 = blockIdx.x * GBN;
    const int m0 = blockIdx.y * GBM;

    float acc[4][8][4];
    #pragma unroll
    for (int a = 0; a < 4; a++)
        #pragma unroll
        for (int b = 0; b < 8; b++)
            #pragma unroll
            for (int c = 0; c < 4; c++) acc[a][b][c] = 0.f;

    const uint32_t aOff = (wm*64 + (lane & 15)) * ASTR3 + (lane >> 4) * 16;
    const uint32_t bOff = OFF3_BH + (wn*64 + (lane & 7) + ((lane >> 4) & 1) * 8) * ASTR3
                        + ((lane >> 3) & 1) * 16;

    load_stage3(smb, Ah, Al, Bh, Bl, m0, n0, 0, tid);
    CP_COMMIT();
    load_stage3(smb + STG3, Ah, Al, Bh, Bl, m0, n0, GBK3, tid);
    CP_COMMIT();

    for (int ch = 0; ch < NCH3; ch++) {
        if (ch < NCH3 - 1) { CP_WAIT(1); } else { CP_WAIT(0); }
        __syncthreads();
        const uint32_t sb = smb + (ch & 1) * STG3;
        #pragma unroll
        for (int ks = 0; ks < 4; ks++) {
            uint32_t ah[4][4], al[4][4], bh[4][4], bl[4][4];
            #pragma unroll
            for (int mt = 0; mt < 4; mt++) {
                ldsm4(ah[mt], sb + aOff + mt * (16*ASTR3) + ks * 32);
                ldsm4(al[mt], sb + OFF3_AL + aOff + mt * (16*ASTR3) + ks * 32);
            }
            #pragma unroll
            for (int np = 0; np < 4; np++) {
                ldsm4(bh[np], sb + bOff + np * (16*ASTR3) + ks * 32);
                ldsm4(bl[np], sb + (OFF3_BL - OFF3_BH) + bOff + np * (16*ASTR3) + ks * 32);
            }
            #pragma unroll
            for (int mt = 0; mt < 4; mt++)
                #pragma unroll
                for (int nt = 0; nt < 8; nt++)
                    hmma_bf16(acc[mt][nt], ah[mt], &bh[nt >> 1][(nt & 1) * 2]);
            #pragma unroll
            for (int mt = 0; mt < 4; mt++)
                #pragma unroll
                for (int nt = 0; nt < 8; nt++)
                    hmma_bf16(acc[mt][nt], ah[mt], &bl[nt >> 1][(nt & 1) * 2]);
            #pragma unroll
            for (int mt = 0; mt < 4; mt++)
                #pragma unroll
                for (int nt = 0; nt < 8; nt++)
                    hmma_bf16(acc[mt][nt], al[mt], &bh[nt >> 1][(nt & 1) * 2]);
        }
        __syncthreads();
        if (ch + 2 < NCH3) {
            load_stage3(smb + (ch & 1) * STG3, Ah, Al, Bh, Bl, m0, n0, (ch + 2) * GBK3, tid);
            CP_COMMIT();
        }
    }

    const int mrow = wm*64 + (lane >> 2);
    const int ncol = n0 + wn*64 + 2*(lane & 3);
    #pragma unroll
    for (int mt = 0; mt < 4; mt++)
        #pragma unroll
        for (int nt = 0; nt < 8; nt++) {
            int r = m0 + mrow + mt*16;
            int cq = ncol + nt*8;
            float2 v0 = make_float2(acc[mt][nt][0], acc[mt][nt][1]);
            float2 v1 = make_float2(acc[mt][nt][2], acc[mt][nt][3]);
            *(float2*)&Y[(size_t)r * 1024 + cq]       = v0;
            *(float2*)&Y[(size_t)(r + 8) * 1024 + cq] = v1;
        }
}

// ================= GEMM 1-term fp16, GBK=64: Y = A16 @ W16.T =================
#define GBK1 64
#define NCH1 (C/GBK1)        // 8
#define NSTAGE1 3
#define ASTR1 144
#define OFF1_B 36864         // 256*144
#define STG1 55296           // + 128*144
#define SMEM1 (NSTAGE1*STG1) // 165888

__device__ __forceinline__ void load_stage1(uint32_t sb,
        const __half* Aw, const __half* Bw,
        int m0, int n0, int k0, int tid) {
    #pragma unroll
    for (int i = 0; i < 8; i++) {
        int q = tid + i*256;
        int r = q >> 3, c = q & 7;
        uint32_t d = sb + r*ASTR1 + c*16;
        size_t g = (size_t)(m0 + r) * C + k0 + c*8;
        CP_ASYNC16(d, Aw + g);
    }
    #pragma unroll
    for (int i = 0; i < 4; i++) {
        int q = tid + i*256;
        int r = q >> 3, c = q & 7;
        uint32_t d = sb + OFF1_B + r*ASTR1 + c*16;
        size_t g = (size_t)(n0 + r) * C + k0 + c*8;
        CP_ASYNC16(d, Bw + g);
    }
}

template<int MODE>
__global__ __launch_bounds__(256, 1)
void tc_gemm1(const __half* __restrict__ Aw, const __half* __restrict__ Bw,
              float* __restrict__ Y, const float* __restrict__ bias,
              const float* __restrict__ resid) {
    extern __shared__ char smc[];
    const uint32_t smb = smem_u32(smc);
    const int tid = threadIdx.x;
    const int lane = tid & 31, wid = tid >> 5;
    const int wm = wid & 3, wn = wid >> 2;        // 4x2 warps, warp tile 64x64
    const int n0 = blockIdx.x * GBN;
    const int m0 = blockIdx.y * GBM;
    const int bb = m0 / HW;
    const int p0 = m0 % HW;

    float acc[4][8][4];
    #pragma unroll
    for (int a = 0; a < 4; a++)
        #pragma unroll
        for (int b = 0; b < 8; b++)
            #pragma unroll
            for (int c = 0; c < 4; c++) acc[a][b][c] = 0.f;

    const uint32_t aOff = (wm*64 + (lane & 15)) * ASTR1 + (lane >> 4) * 16;
    const uint32_t bOff = OFF1_B + (wn*64 + (lane & 7) + ((lane >> 4) & 1) * 8) * ASTR1
                        + ((lane >> 3) & 1) * 16;

    load_stage1(smb, Aw, Bw, m0, n0, 0, tid);
    CP_COMMIT();
    load_stage1(smb + STG1, Aw, Bw, m0, n0, GBK1, tid);
    CP_COMMIT();

    int stg = 0;
    for (int ch = 0; ch < NCH1; ch++) {
        if (ch < NCH1 - 1) { CP_WAIT(1); } else { CP_WAIT(0); }
        __syncthreads();
        if (ch + 2 < NCH1) {
            int ps = stg + 2; if (ps >= NSTAGE1) ps -= NSTAGE1;
            load_stage1(smb + ps * STG1, Aw, Bw, m0, n0, (ch + 2) * GBK1, tid);
            CP_COMMIT();
        }
        const uint32_t sb = smb + stg * STG1;
        #pragma unroll
        for (int ks = 0; ks < 4; ks++) {
            uint32_t ah[4][4], bh[4][4];
            #pragma unroll
            for (int mt = 0; mt < 4; mt++)
                ldsm4(ah[mt], sb + aOff + mt * (16*ASTR1) + ks * 32);
            #pragma unroll
            for (int np = 0; np < 4; np++)
                ldsm4(bh[np], sb + bOff + np * (16*ASTR1) + ks * 32);
            #pragma unroll
            for (int mt = 0; mt < 4; mt++)
                #pragma unroll
                for (int nt = 0; nt < 8; nt++)
                    hmma_f16(acc[mt][nt], ah[mt], &bh[nt >> 1][(nt & 1) * 2]);
        }
        stg++; if (stg == NSTAGE1) stg = 0;
    }

    const int mrow = wm*64 + (lane >> 2);
    const int ncol = n0 + wn*64 + 2*(lane & 3);
    if (MODE == 0) {
        #pragma unroll
        for (int mt = 0; mt < 4; mt++)
            #pragma unroll
            for (int nt = 0; nt < 8; nt++) {
                int r = m0 + mrow + mt*16;
                int cq = ncol + nt*8;
                float2 v0 = make_float2(acc[mt][nt][0], acc[mt][nt][1]);
                float2 v1 = make_float2(acc[mt][nt][2], acc[mt][nt][3]);
                *(float2*)&Y[(size_t)r * C + cq]       = v0;
                *(float2*)&Y[(size_t)(r + 8) * C + cq] = v1;
            }
    } else {
        #pragma unroll
        for (int mt = 0; mt < 4; mt++)
            #pragma unroll
            for (int nt = 0; nt < 8; nt++) {
                int p = p0 + mrow + mt*16;
                int j = ncol + nt*8;
                float bj0 = bias[j], bj1 = bias[j + 1];
                size_t a00 = (size_t)bb*C*HW + (size_t)j*HW + p;
                Y[a00]          = acc[mt][nt][0] + bj0 + resid[a00];
                Y[a00 + HW]     = acc[mt][nt][1] + bj1 + resid[a00 + HW];
                Y[a00 + 8]      = acc[mt][nt][2] + bj0 + resid[a00 + 8];
                Y[a00 + HW + 8] = acc[mt][nt][3] + bj1 + resid[a00 + HW + 8];
            }
    }
}

// ---------------- dots: warp per (b,n); all 64 (i,j) pairs ----------------
__global__ void dots_kernel() {
    __shared__ float sQ[8][512];
    __shared__ float sK[8][512];
    int w = threadIdx.x >> 5, lane = threadIdx.x & 31;
    int m = blockIdx.x * 8 + w;                 // < 32768
    int b = m >> 12, n = m & 4095;
    const float4* q4 = (const float4*)(g_qk + (size_t)m * 1024);
    const float4* k4 = q4 + 128;                // K half of the row
    #pragma unroll
    for (int i = 0; i < 4; i++) {
        ((float4*)sQ[w])[lane + i*32] = q4[lane + i*32];
        ((float4*)sK[w])[lane + i*32] = k4[lane + i*32];
    }
    __syncwarp();
    #pragma unroll
    for (int t = 0; t < 2; t++) {
        int p = lane + t*32;                    // 0..63
        int i = p >> 3, j = p & 7;
        const float* qi = &sQ[w][i * HD];
        const float* kj = &sK[w][j * HD];
        float acc = 0.f;
        #pragma unroll
        for (int d = 0; d < HD; d++) acc += qi[d] * kj[d];
        g_att[(size_t)(b*64 + p) * HW + n] = acc * SCALE_ATT;
    }
}

// ---------------- softmax over n per (b,i,j) row, in place ----------------
__global__ void softmax_kernel() {
    float* row = g_att + (size_t)blockIdx.x * HW;
    __shared__ float sh[256];
    int tid = threadIdx.x;

    float mx = -1e30f;
    for (int n = tid; n < HW; n += 256) mx = fmaxf(mx, row[n]);
    sh[tid] = mx; __syncthreads();
    for (int off = 128; off > 0; off >>= 1) {
        if (tid < off) sh[tid] = fmaxf(sh[tid], sh[tid + off]);
        __syncthreads();
    }
    mx = sh[0]; __syncthreads();

    float sum = 0.f;
    for (int n = tid; n < HW; n += 256) sum += __expf(row[n] - mx);
    sh[tid] = sum; __syncthreads();
    for (int off = 128; off > 0; off >>= 1) {
        if (tid < off) sh[tid] += sh[tid + off];
        __syncthreads();
    }
    float inv = 1.f / sh[0];

    for (int n = tid; n < HW; n += 256) row[n] = __expf(row[n] - mx) * inv;
}

// ---------------- attv: ao[m, i*64+d] = sum_j att[b,i,j,n] * V[m, j*64+d]; fp16 ----------------
__global__ void attv_kernel() {
    size_t idx = (size_t)blockIdx.x * 256 + threadIdx.x;  // < M_TOT*C
    int m  = (int)(idx >> 9);
    int cc = (int)(idx & 511);
    int b = m >> 12, n = m & 4095;
    int i = cc >> 6, d = cc & 63;
    const float* att = g_att + ((size_t)(b*64 + i*8)) * HW + n;
    const float* v   = g_v + (size_t)m * C + d;
    float acc = 0.f;
    #pragma unroll
    for (int j = 0; j < NHEAD; j++)
        acc += att[(size_t)j * HW] * v[j * HD];
    g_ao_h[idx] = __float2half(acc);
}

// ---------------- launch (single stream, serial) ----------------
extern "C" void kernel_launch(void* const* d_in, const int* in_sizes, int n_in,
                              void* d_out, int out_size) {
    const float* x     = (const float*)d_in[0];
    const float* gamma = (const float*)d_in[1];
    const float* beta  = (const float*)d_in[2];
    const float* Wq    = (const float*)d_in[3];
    const float* Wk    = (const float*)d_in[4];
    const float* Wv    = (const float*)d_in[5];
    const float* Wp    = (const float*)d_in[6];
    const float* bp    = (const float*)d_in[7];
    float* out = (float*)d_out;

    float *p_xn, *p_qk, *p_v;
    __nv_bfloat16 *p_xah, *p_xal, *p_wh, *p_wl;
    __half *p_x16h, *p_w16, *p_aoh;
    cudaGetSymbolAddress((void**)&p_xn,   g_xn);
    cudaGetSymbolAddress((void**)&p_qk,   g_qk);
    cudaGetSymbolAddress((void**)&p_v,    g_v);
    cudaGetSymbolAddress((void**)&p_xah,  g_xa_hi);
    cudaGetSymbolAddress((void**)&p_xal,  g_xa_lo);
    cudaGetSymbolAddress((void**)&p_wh,   g_w_hi);
    cudaGetSymbolAddress((void**)&p_wl,   g_w_lo);
    cudaGetSymbolAddress((void**)&p_x16h, g_x16h);
    cudaGetSymbolAddress((void**)&p_w16,  g_w16);
    cudaGetSymbolAddress((void**)&p_aoh,  g_ao_h);

    cudaFuncSetAttribute(tc_gemm3,    cudaFuncAttributeMaxDynamicSharedMemorySize, SMEM3);
    cudaFuncSetAttribute(tc_gemm1<0>, cudaFuncAttributeMaxDynamicSharedMemorySize, SMEM1);
    cudaFuncSetAttribute(tc_gemm1<1>, cudaFuncAttributeMaxDynamicSharedMemorySize, SMEM1);

    gn_stats_kernel<<<B*NG, 512>>>(x);
    gn_split_kernel<<<dim3(HW/32, C/32, B), dim3(32, 8)>>>(x, gamma, beta);
    split_w_kernel<<<2*C*C/256, 256>>>(Wq, Wk, Wv, Wp);

    // fused Q|K GEMM: N = 1024, bf16 3-term (argmax-critical path)
    dim3 g3(1024/GBN, M_TOT/GBM);   // (8, 128)
    tc_gemm3<<<g3, 256, SMEM3>>>(p_xah, p_xal, p_wh, p_wl, p_qk);

    // V GEMM (fp16 1-term)
    dim3 g2(C/GBN, M_TOT/GBM);      // (4, 128)
    tc_gemm1<0><<<g2, 256, SMEM1>>>(p_x16h, p_w16, p_v, nullptr, nullptr);

    dots_kernel<<<M_TOT/8, 256>>>();
    softmax_kernel<<<B*NHEAD*NHEAD, 256>>>();
    attv_kernel<<<(unsigned)(M_TOT*(size_t)C/256), 256>>>();

    // proj GEMM (fp16 1-term) + bias + residual
    tc_gemm1<1><<<g2, 256, SMEM1>>>(p_aoh, p_w16 + (size_t)C*C, out, bp, p_xn);
}

// round 16
// speedup vs baseline: 1.4578x; 1.0502x over previous
#include <cuda_runtime.h>
#include <cuda_bf16.h>
#include <cuda_fp16.h>
#include <cstdint>
#include <cstddef>

#define B 8
#define C 512
#define HW 4096
#define M_TOT (B*HW)          // 32768
#define NG 32
#define CPG (C/NG)            // 16
#define GRP_ELEMS (CPG*HW)    // 65536
#define NHEAD 8
#define HD 64
#define EPS_GN 1e-6f
#define SCALE_ATT 8.0f        // sqrt(64), reference MULTIPLIES

// ---------------- scratch ----------------
__device__ float g_xn [B*C*HW];                 // normalized x, (b,c,p) fp32 (residual)
__device__ float g_qk [(size_t)M_TOT*1024];     // [Q | K] row-major, stride 1024
__device__ float g_v  [M_TOT*C];
__device__ float g_att[B*NHEAD*NHEAD*HW];       // dots then att, (b,i,j,n)
__device__ float g_att_t[(size_t)B*HW*64];      // att transposed: (b, n, ij)
__device__ __nv_bfloat16 g_xa_hi[M_TOT*C];      // xn row-major (m,k) bf16 split (QK path)
__device__ __nv_bfloat16 g_xa_lo[M_TOT*C];
__device__ __half g_x16h[M_TOT*C];              // xn row-major fp16 (V path)
__device__ __nv_bfloat16 g_w_hi[2*C*C];         // [Wq;Wk] bf16 split (j,k)
__device__ __nv_bfloat16 g_w_lo[2*C*C];
__device__ __half g_w16[2*C*C];                 // [Wv;Wp] fp16 (j,k)
__device__ __half g_ao_h[M_TOT*C];              // attention out fp16 (m,c)
__device__ float g_mean[B*NG];
__device__ float g_rstd[B*NG];

// ---------------- helpers ----------------
__device__ __forceinline__ uint32_t smem_u32(const void* p) {
    uint32_t a;
    asm("{ .reg .u64 t; cvta.to.shared.u64 t, %1; cvt.u32.u64 %0, t; }" : "=r"(a) : "l"(p));
    return a;
}
#define CP_ASYNC16(s, g)  asm volatile("cp.async.cg.shared.global [%0], [%1], 16;" :: "r"(s), "l"(g))
#define CP_COMMIT()       asm volatile("cp.async.commit_group;" ::: "memory")
#define CP_WAIT(n)        asm volatile("cp.async.wait_group %0;" :: "n"(n) : "memory")

__device__ __forceinline__ void ldsm4(uint32_t* r, uint32_t addr) {
    asm volatile("ldmatrix.sync.aligned.m8n8.x4.shared.b16 {%0,%1,%2,%3}, [%4];"
        : "=r"(r[0]), "=r"(r[1]), "=r"(r[2]), "=r"(r[3]) : "r"(addr));
}
__device__ __forceinline__ void hmma_bf16(float* c, const uint32_t* a, const uint32_t* b) {
    asm volatile("mma.sync.aligned.m16n8k16.row.col.f32.bf16.bf16.f32 "
        "{%0,%1,%2,%3}, {%4,%5,%6,%7}, {%8,%9}, {%0,%1,%2,%3};"
        : "+f"(c[0]), "+f"(c[1]), "+f"(c[2]), "+f"(c[3])
        : "r"(a[0]), "r"(a[1]), "r"(a[2]), "r"(a[3]), "r"(b[0]), "r"(b[1]));
}
__device__ __forceinline__ void hmma_f16(float* c, const uint32_t* a, const uint32_t* b) {
    asm volatile("mma.sync.aligned.m16n8k16.row.col.f32.f16.f16.f32 "
        "{%0,%1,%2,%3}, {%4,%5,%6,%7}, {%8,%9}, {%0,%1,%2,%3};"
        : "+f"(c[0]), "+f"(c[1]), "+f"(c[2]), "+f"(c[3])
        : "r"(a[0]), "r"(a[1]), "r"(a[2]), "r"(a[3]), "r"(b[0]), "r"(b[1]));
}

// ---------------- GroupNorm: stats ----------------
__global__ void gn_stats_kernel(const float* __restrict__ x) {
    int grp = blockIdx.x;
    const float* p = x + (size_t)grp * GRP_ELEMS;
    float s = 0.f, s2 = 0.f;
    for (int i = threadIdx.x; i < GRP_ELEMS; i += blockDim.x) {
        float v = p[i]; s += v; s2 += v * v;
    }
    __shared__ float sh[512], sh2[512];
    sh[threadIdx.x] = s; sh2[threadIdx.x] = s2;
    __syncthreads();
    for (int off = blockDim.x >> 1; off > 0; off >>= 1) {
        if (threadIdx.x < off) {
            sh[threadIdx.x]  += sh[threadIdx.x + off];
            sh2[threadIdx.x] += sh2[threadIdx.x + off];
        }
        __syncthreads();
    }
    if (threadIdx.x == 0) {
        float mean = sh[0] * (1.0f / GRP_ELEMS);
        float var  = sh2[0] * (1.0f / GRP_ELEMS) - mean * mean;
        g_mean[grp] = mean;
        g_rstd[grp] = rsqrtf(var + EPS_GN);
    }
}

// ---------------- fused GroupNorm-apply + transpose + splits ----------------
__global__ void gn_split_kernel(const float* __restrict__ x,
                                const float* __restrict__ gamma,
                                const float* __restrict__ beta) {
    __shared__ float sm[32][33];
    int p0 = blockIdx.x * 32, c0 = blockIdx.y * 32, b = blockIdx.z;
    int tx = threadIdx.x, ty = threadIdx.y;     // (32, 8)
    #pragma unroll
    for (int i = 0; i < 4; i++) {
        int c = c0 + ty + i*8;
        int grp = b*NG + (c >> 4);
        float m = g_mean[grp], r = g_rstd[grp];
        float ga = gamma[c], be = beta[c];
        size_t o = (size_t)b*C*HW + (size_t)c*HW + p0 + tx;
        float v = (x[o] - m) * r * ga + be;
        g_xn[o] = v;
        sm[ty + i*8][tx] = v;
    }
    __syncthreads();
    #pragma unroll
    for (int i = 0; i < 4; i++) {
        int p = p0 + ty + i*8;
        float v = sm[tx][ty + i*8];
        size_t o = (size_t)(b*HW + p) * C + c0 + tx;
        __nv_bfloat16 h = __float2bfloat16(v);
        g_xa_hi[o] = h;
        g_xa_lo[o] = __float2bfloat16(v - __bfloat162float(h));
        g_x16h[o] = __float2half(v);
    }
}

// ---------------- split weights ----------------
__global__ void split_w_kernel(const float* __restrict__ Wq, const float* __restrict__ Wk,
                               const float* __restrict__ Wv, const float* __restrict__ Wp) {
    int idx = blockIdx.x * 256 + threadIdx.x;   // < 2*C*C
    int wsel = idx >> 18;
    int off  = idx & (C*C - 1);
    float vqk = (wsel == 0) ? Wq[off] : Wk[off];
    __nv_bfloat16 h = __float2bfloat16(vqk);
    g_w_hi[idx] = h;
    g_w_lo[idx] = __float2bfloat16(vqk - __bfloat162float(h));
    float vvp = (wsel == 0) ? Wv[off] : Wp[off];
    g_w16[idx] = __float2half(vvp);
}

// ======= GEMM 3-term bf16 (QK fused): 128 threads, 2 CTAs/SM, GBK=32, 2-stage =======
#define GBM 128
#define GBN 128
#define GBK3 32
#define NCH3 (C/GBK3)        // 16
#define ASTR3 80
#define OFF3_AL 10240        // 128*80
#define OFF3_BH 20480
#define OFF3_BL 30720
#define STG3 40960
#define SMEM3 (2*STG3)       // 81920 -> 2 CTAs/SM

__device__ __forceinline__ void load_stage3(uint32_t sb,
        const __nv_bfloat16* Ah, const __nv_bfloat16* Al,
        const __nv_bfloat16* Bh, const __nv_bfloat16* Bl,
        int m0, int n0, int k0, int tid) {
    #pragma unroll
    for (int i = 0; i < 4; i++) {
        int q = tid + i*128;
        int r = q >> 2, c = q & 3;
        uint32_t d = sb + r*ASTR3 + c*16;
        size_t gA = (size_t)(m0 + r) * C + k0 + c*8;
        size_t gB = (size_t)(n0 + r) * C + k0 + c*8;
        CP_ASYNC16(d, Ah + gA);
        CP_ASYNC16(d + OFF3_AL, Al + gA);
        CP_ASYNC16(d + OFF3_BH, Bh + gB);
        CP_ASYNC16(d + OFF3_BL, Bl + gB);
    }
}

__global__ __launch_bounds__(128, 2)
void tc_gemm3(const __nv_bfloat16* __restrict__ Ah, const __nv_bfloat16* __restrict__ Al,
              const __nv_bfloat16* __restrict__ Bh, const __nv_bfloat16* __restrict__ Bl,
              float* __restrict__ Y) {
    extern __shared__ char smc[];
    const uint32_t smb = smem_u32(smc);
    const int tid = threadIdx.x;
    const int lane = tid & 31, wid = tid >> 5;
    const int wm = wid & 1, wn = wid >> 1;        // 2x2 warps, warp tile 64x64
    const int n0 = blockIdx.x * GBN;
    const int m0 = blockIdx.y * GBM;

    float acc[4][8][4];
    #pragma unroll
    for (int a = 0; a < 4; a++)
        #pragma unroll
        for (int b = 0; b < 8; b++)
            #pragma unroll
            for (int c = 0; c < 4; c++) acc[a][b][c] = 0.f;

    const uint32_t aOff = (wm*64 + (lane & 15)) * ASTR3 + (lane >> 4) * 16;
    const uint32_t bOff = OFF3_BH + (wn*64 + (lane & 7) + ((lane >> 4) & 1) * 8) * ASTR3
                        + ((lane >> 3) & 1) * 16;

    load_stage3(smb, Ah, Al, Bh, Bl, m0, n0, 0, tid);
    CP_COMMIT();
    load_stage3(smb + STG3, Ah, Al, Bh, Bl, m0, n0, GBK3, tid);
    CP_COMMIT();

    for (int ch = 0; ch < NCH3; ch++) {
        if (ch < NCH3 - 1) { CP_WAIT(1); } else { CP_WAIT(0); }
        __syncthreads();
        const uint32_t sb = smb + (ch & 1) * STG3;
        #pragma unroll
        for (int ks = 0; ks < 2; ks++) {
            uint32_t ah[4][4], al[4][4], bh[4][4], bl[4][4];
            #pragma unroll
            for (int mt = 0; mt < 4; mt++) {
                ldsm4(ah[mt], sb + aOff + mt * (16*ASTR3) + ks * 32);
                ldsm4(al[mt], sb + OFF3_AL + aOff + mt * (16*ASTR3) + ks * 32);
            }
            #pragma unroll
            for (int np = 0; np < 4; np++) {
                ldsm4(bh[np], sb + bOff + np * (16*ASTR3) + ks * 32);
                ldsm4(bl[np], sb + (OFF3_BL - OFF3_BH) + bOff + np * (16*ASTR3) + ks * 32);
            }
            #pragma unroll
            for (int mt = 0; mt < 4; mt++)
                #pragma unroll
                for (int nt = 0; nt < 8; nt++)
                    hmma_bf16(acc[mt][nt], ah[mt], &bh[nt >> 1][(nt & 1) * 2]);
            #pragma unroll
            for (int mt = 0; mt < 4; mt++)
                #pragma unroll
                for (int nt = 0; nt < 8; nt++)
                    hmma_bf16(acc[mt][nt], ah[mt], &bl[nt >> 1][(nt & 1) * 2]);
            #pragma unroll
            for (int mt = 0; mt < 4; mt++)
                #pragma unroll
                for (int nt = 0; nt < 8; nt++)
                    hmma_bf16(acc[mt][nt], al[mt], &bh[nt >> 1][(nt & 1) * 2]);
        }
        __syncthreads();
        if (ch + 2 < NCH3) {
            load_stage3(smb + (ch & 1) * STG3, Ah, Al, Bh, Bl, m0, n0, (ch + 2) * GBK3, tid);
            CP_COMMIT();
        }
    }

    const int mrow = wm*64 + (lane >> 2);
    const int ncol = n0 + wn*64 + 2*(lane & 3);
    #pragma unroll
    for (int mt = 0; mt < 4; mt++)
        #pragma unroll
        for (int nt = 0; nt < 8; nt++) {
            int r = m0 + mrow + mt*16;
            int cq = ncol + nt*8;
            float2 v0 = make_float2(acc[mt][nt][0], acc[mt][nt][1]);
            float2 v1 = make_float2(acc[mt][nt][2], acc[mt][nt][3]);
            *(float2*)&Y[(size_t)r * 1024 + cq]       = v0;
            *(float2*)&Y[(size_t)(r + 8) * 1024 + cq] = v1;
        }
}

// ======= GEMM 1-term fp16: 128 threads, 2 CTAs/SM, GBK=64, 2-stage =======
#define GBK1 64
#define NCH1 (C/GBK1)        // 8
#define ASTR1 144
#define OFF1_B 18432         // 128*144
#define STG1 36864
#define SMEM1 (2*STG1)       // 73728 -> 2 CTAs/SM

__device__ __forceinline__ void load_stage1(uint32_t sb,
        const __half* Aw, const __half* Bw,
        int m0, int n0, int k0, int tid) {
    #pragma unroll
    for (int i = 0; i < 8; i++) {
        int q = tid + i*128;
        int r = q >> 3, c = q & 7;
        uint32_t d = sb + r*ASTR1 + c*16;
        size_t gA = (size_t)(m0 + r) * C + k0 + c*8;
        size_t gB = (size_t)(n0 + r) * C + k0 + c*8;
        CP_ASYNC16(d, Aw + gA);
        CP_ASYNC16(d + OFF1_B, Bw + gB);
    }
}

template<int MODE>
__global__ __launch_bounds__(128, 2)
void tc_gemm1(const __half* __restrict__ Aw, const __half* __restrict__ Bw,
              float* __restrict__ Y, const float* __restrict__ bias,
              const float* __restrict__ resid) {
    extern __shared__ char smc[];
    const uint32_t smb = smem_u32(smc);
    const int tid = threadIdx.x;
    const int lane = tid & 31, wid = tid >> 5;
    const int wm = wid & 1, wn = wid >> 1;        // 2x2 warps, warp tile 64x64
    const int n0 = blockIdx.x * GBN;
    const int m0 = blockIdx.y * GBM;
    const int bb = m0 / HW;
    const int p0 = m0 % HW;

    float acc[4][8][4];
    #pragma unroll
    for (int a = 0; a < 4; a++)
        #pragma unroll
        for (int b = 0; b < 8; b++)
            #pragma unroll
            for (int c = 0; c < 4; c++) acc[a][b][c] = 0.f;

    const uint32_t aOff = (wm*64 + (lane & 15)) * ASTR1 + (lane >> 4) * 16;
    const uint32_t bOff = OFF1_B + (wn*64 + (lane & 7) + ((lane >> 4) & 1) * 8) * ASTR1
                        + ((lane >> 3) & 1) * 16;

    load_stage1(smb, Aw, Bw, m0, n0, 0, tid);
    CP_COMMIT();
    load_stage1(smb + STG1, Aw, Bw, m0, n0, GBK1, tid);
    CP_COMMIT();

    for (int ch = 0; ch < NCH1; ch++) {
        if (ch < NCH1 - 1) { CP_WAIT(1); } else { CP_WAIT(0); }
        __syncthreads();
        const uint32_t sb = smb + (ch & 1) * STG1;
        #pragma unroll
        for (int ks = 0; ks < 4; ks++) {
            uint32_t ah[4][4], bh[4][4];
            #pragma unroll
            for (int mt = 0; mt < 4; mt++)
                ldsm4(ah[mt], sb + aOff + mt * (16*ASTR1) + ks * 32);
            #pragma unroll
            for (int np = 0; np < 4; np++)
                ldsm4(bh[np], sb + bOff + np * (16*ASTR1) + ks * 32);
            #pragma unroll
            for (int mt = 0; mt < 4; mt++)
                #pragma unroll
                for (int nt = 0; nt < 8; nt++)
                    hmma_f16(acc[mt][nt], ah[mt], &bh[nt >> 1][(nt & 1) * 2]);
        }
        __syncthreads();
        if (ch + 2 < NCH1) {
            load_stage1(smb + (ch & 1) * STG1, Aw, Bw, m0, n0, (ch + 2) * GBK1, tid);
            CP_COMMIT();
        }
    }

    const int mrow = wm*64 + (lane >> 2);
    const int ncol = n0 + wn*64 + 2*(lane & 3);
    if (MODE == 0) {
        #pragma unroll
        for (int mt = 0; mt < 4; mt++)
            #pragma unroll
            for (int nt = 0; nt < 8; nt++) {
                int r = m0 + mrow + mt*16;
                int cq = ncol + nt*8;
                float2 v0 = make_float2(acc[mt][nt][0], acc[mt][nt][1]);
                float2 v1 = make_float2(acc[mt][nt][2], acc[mt][nt][3]);
                *(float2*)&Y[(size_t)r * C + cq]       = v0;
                *(float2*)&Y[(size_t)(r + 8) * C + cq] = v1;
            }
    } else {
        #pragma unroll
        for (int mt = 0; mt < 4; mt++)
            #pragma unroll
            for (int nt = 0; nt < 8; nt++) {
                int p = p0 + mrow + mt*16;
                int j = ncol + nt*8;
                float bj0 = bias[j], bj1 = bias[j + 1];
                size_t a00 = (size_t)bb*C*HW + (size_t)j*HW + p;
                Y[a00]          = acc[mt][nt][0] + bj0 + resid[a00];
                Y[a00 + HW]     = acc[mt][nt][1] + bj1 + resid[a00 + HW];
                Y[a00 + 8]      = acc[mt][nt][2] + bj0 + resid[a00 + 8];
                Y[a00 + HW + 8] = acc[mt][nt][3] + bj1 + resid[a00 + HW + 8];
            }
    }
}

// ---------------- dots: warp per (b,n); all 64 (i,j) pairs ----------------
__global__ void dots_kernel() {
    __shared__ float sQ[8][512];
    __shared__ float sK[8][512];
    int w = threadIdx.x >> 5, lane = threadIdx.x & 31;
    int m = blockIdx.x * 8 + w;                 // < 32768
    int b = m >> 12, n = m & 4095;
    const float4* q4 = (const float4*)(g_qk + (size_t)m * 1024);
    const float4* k4 = q4 + 128;                // K half of the row
    #pragma unroll
    for (int i = 0; i < 4; i++) {
        ((float4*)sQ[w])[lane + i*32] = q4[lane + i*32];
        ((float4*)sK[w])[lane + i*32] = k4[lane + i*32];
    }
    __syncwarp();
    #pragma unroll
    for (int t = 0; t < 2; t++) {
        int p = lane + t*32;                    // 0..63
        int i = p >> 3, j = p & 7;
        const float* qi = &sQ[w][i * HD];
        const float* kj = &sK[w][j * HD];
        float acc = 0.f;
        #pragma unroll
        for (int d = 0; d < HD; d++) acc += qi[d] * kj[d];
        g_att[(size_t)(b*64 + p) * HW + n] = acc * SCALE_ATT;
    }
}

// ---------------- softmax over n per (b,i,j) row, in place ----------------
__global__ void softmax_kernel() {
    float* row = g_att + (size_t)blockIdx.x * HW;
    __shared__ float sh[256];
    int tid = threadIdx.x;

    float mx = -1e30f;
    for (int n = tid; n < HW; n += 256) mx = fmaxf(mx, row[n]);
    sh[tid] = mx; __syncthreads();
    for (int off = 128; off > 0; off >>= 1) {
        if (tid < off) sh[tid] = fmaxf(sh[tid], sh[tid + off]);
        __syncthreads();
    }
    mx = sh[0]; __syncthreads();

    float sum = 0.f;
    for (int n = tid; n < HW; n += 256) sum += __expf(row[n] - mx);
    sh[tid] = sum; __syncthreads();
    for (int off = 128; off > 0; off >>= 1) {
        if (tid < off) sh[tid] += sh[tid + off];
        __syncthreads();
    }
    float inv = 1.f / sh[0];

    for (int n = tid; n < HW; n += 256) row[n] = __expf(row[n] - mx) * inv;
}

// ---------------- transpose att: (b, ij, n) -> (b, n, ij) ----------------
__global__ void att_tr_kernel() {
    __shared__ float sm[64][65];
    int n0 = blockIdx.x * 64, b = blockIdx.y;
    int tx = threadIdx.x, ty = threadIdx.y;     // (64, 8)
    #pragma unroll
    for (int i = 0; i < 8; i++) {
        int ij = ty + i*8;
        sm[ij][tx] = g_att[((size_t)(b*64 + ij)) * HW + n0 + tx];
    }
    __syncthreads();
    #pragma unroll
    for (int i = 0; i < 8; i++) {
        int n = n0 + ty + i*8;
        g_att_t[((size_t)b*HW + n) * 64 + tx] = sm[tx][ty + i*8];
    }
}

// ---------------- attv: coalesced att_t reads; fp16 out ----------------
__global__ void attv_kernel() {
    size_t idx = (size_t)blockIdx.x * 256 + threadIdx.x;  // < M_TOT*C
    int m  = (int)(idx >> 9);
    int cc = (int)(idx & 511);
    int i = cc >> 6, d = cc & 63;
    const float* att = g_att_t + (size_t)m * 64 + i*8;    // contiguous 8 floats
    const float* v   = g_v + (size_t)m * C + d;
    float acc = 0.f;
    #pragma unroll
    for (int j = 0; j < NHEAD; j++)
        acc += att[j] * v[j * HD];
    g_ao_h[idx] = __float2half(acc);
}

// ---------------- launch (single stream, serial) ----------------
extern "C" void kernel_launch(void* const* d_in, const int* in_sizes, int n_in,
                              void* d_out, int out_size) {
    const float* x     = (const float*)d_in[0];
    const float* gamma = (const float*)d_in[1];
    const float* beta  = (const float*)d_in[2];
    const float* Wq    = (const float*)d_in[3];
    const float* Wk    = (const float*)d_in[4];
    const float* Wv    = (const float*)d_in[5];
    const float* Wp    = (const float*)d_in[6];
    const float* bp    = (const float*)d_in[7];
    float* out = (float*)d_out;

    float *p_xn, *p_qk, *p_v;
    __nv_bfloat16 *p_xah, *p_xal, *p_wh, *p_wl;
    __half *p_x16h, *p_w16, *p_aoh;
    cudaGetSymbolAddress((void**)&p_xn,   g_xn);
    cudaGetSymbolAddress((void**)&p_qk,   g_qk);
    cudaGetSymbolAddress((void**)&p_v,    g_v);
    cudaGetSymbolAddress((void**)&p_xah,  g_xa_hi);
    cudaGetSymbolAddress((void**)&p_xal,  g_xa_lo);
    cudaGetSymbolAddress((void**)&p_wh,   g_w_hi);
    cudaGetSymbolAddress((void**)&p_wl,   g_w_lo);
    cudaGetSymbolAddress((void**)&p_x16h, g_x16h);
    cudaGetSymbolAddress((void**)&p_w16,  g_w16);
    cudaGetSymbolAddress((void**)&p_aoh,  g_ao_h);

    cudaFuncSetAttribute(tc_gemm3,    cudaFuncAttributeMaxDynamicSharedMemorySize, SMEM3);
    cudaFuncSetAttribute(tc_gemm1<0>, cudaFuncAttributeMaxDynamicSharedMemorySize, SMEM1);
    cudaFuncSetAttribute(tc_gemm1<1>, cudaFuncAttributeMaxDynamicSharedMemorySize, SMEM1);

    gn_stats_kernel<<<B*NG, 512>>>(x);
    gn_split_kernel<<<dim3(HW/32, C/32, B), dim3(32, 8)>>>(x, gamma, beta);
    split_w_kernel<<<2*C*C/256, 256>>>(Wq, Wk, Wv, Wp);

    // fused Q|K GEMM: N = 1024, bf16 3-term (argmax-critical path)
    dim3 g3(1024/GBN, M_TOT/GBM);   // (8, 256) = 2048 CTAs
    tc_gemm3<<<g3, 128, SMEM3>>>(p_xah, p_xal, p_wh, p_wl, p_qk);

    // V GEMM (fp16 1-term)
    dim3 g2(C/GBN, M_TOT/GBM);      // (4, 256) = 1024 CTAs
    tc_gemm1<0><<<g2, 128, SMEM1>>>(p_x16h, p_w16, p_v, nullptr, nullptr);

    dots_kernel<<<M_TOT/8, 256>>>();
    softmax_kernel<<<B*NHEAD*NHEAD, 256>>>();
    att_tr_kernel<<<dim3(HW/64, B), dim3(64, 8)>>>();
    attv_kernel<<<(unsigned)(M_TOT*(size_t)C/256), 256>>>();

    // proj GEMM (fp16 1-term) + bias + residual
    tc_gemm1<1><<<g2, 128, SMEM1>>>(p_aoh, p_w16 + (size_t)C*C, out, bp, p_xn);
}

// round 17
// speedup vs baseline: 1.6485x; 1.1308x over previous
#include <cuda_runtime.h>
#include <cuda_bf16.h>
#include <cuda_fp16.h>
#include <cstdint>
#include <cstddef>

#define B 8
#define C 512
#define HW 4096
#define M_TOT (B*HW)          // 32768
#define NG 32
#define CPG (C/NG)            // 16
#define GRP_ELEMS (CPG*HW)    // 65536
#define NHEAD 8
#define HD 64
#define EPS_GN 1e-6f
#define SCALE_ATT 8.0f        // sqrt(64), reference MULTIPLIES

// ---------------- scratch ----------------
__device__ float g_xn [B*C*HW];                 // normalized x, (b,c,p) fp32 (residual)
__device__ float g_qk [(size_t)M_TOT*1024];     // [Q | K] row-major, stride 1024
__device__ float g_v  [M_TOT*C];
__device__ float g_att[B*NHEAD*NHEAD*HW];       // dots then att, (b,i,j,n)
__device__ float g_att_t[(size_t)B*HW*64];      // att transposed: (b, n, ij)
__device__ __half g_x16h[M_TOT*C];              // xn row-major fp16 hi
__device__ __half g_x16l[M_TOT*C];              // xn row-major fp16 lo
__device__ __half g_w16qk[2*C*C];               // [Wq;Wk] fp16 (j,k)
__device__ __half g_w16[2*C*C];                 // [Wv;Wp] fp16 (j,k)
__device__ __half g_ao_h[M_TOT*C];              // attention out fp16 (m,c)
__device__ float g_mean[B*NG];
__device__ float g_rstd[B*NG];

// ---------------- helpers ----------------
__device__ __forceinline__ uint32_t smem_u32(const void* p) {
    uint32_t a;
    asm("{ .reg .u64 t; cvta.to.shared.u64 t, %1; cvt.u32.u64 %0, t; }" : "=r"(a) : "l"(p));
    return a;
}
#define CP_ASYNC16(s, g)  asm volatile("cp.async.cg.shared.global [%0], [%1], 16;" :: "r"(s), "l"(g))
#define CP_COMMIT()       asm volatile("cp.async.commit_group;" ::: "memory")
#define CP_WAIT(n)        asm volatile("cp.async.wait_group %0;" :: "n"(n) : "memory")

__device__ __forceinline__ void ldsm4(uint32_t* r, uint32_t addr) {
    asm volatile("ldmatrix.sync.aligned.m8n8.x4.shared.b16 {%0,%1,%2,%3}, [%4];"
        : "=r"(r[0]), "=r"(r[1]), "=r"(r[2]), "=r"(r[3]) : "r"(addr));
}
__device__ __forceinline__ void hmma_f16(float* c, const uint32_t* a, const uint32_t* b) {
    asm volatile("mma.sync.aligned.m16n8k16.row.col.f32.f16.f16.f32 "
        "{%0,%1,%2,%3}, {%4,%5,%6,%7}, {%8,%9}, {%0,%1,%2,%3};"
        : "+f"(c[0]), "+f"(c[1]), "+f"(c[2]), "+f"(c[3])
        : "r"(a[0]), "r"(a[1]), "r"(a[2]), "r"(a[3]), "r"(b[0]), "r"(b[1]));
}

// ---------------- GroupNorm: stats ----------------
__global__ void gn_stats_kernel(const float* __restrict__ x) {
    int grp = blockIdx.x;
    const float* p = x + (size_t)grp * GRP_ELEMS;
    float s = 0.f, s2 = 0.f;
    for (int i = threadIdx.x; i < GRP_ELEMS; i += blockDim.x) {
        float v = p[i]; s += v; s2 += v * v;
    }
    __shared__ float sh[512], sh2[512];
    sh[threadIdx.x] = s; sh2[threadIdx.x] = s2;
    __syncthreads();
    for (int off = blockDim.x >> 1; off > 0; off >>= 1) {
        if (threadIdx.x < off) {
            sh[threadIdx.x]  += sh[threadIdx.x + off];
            sh2[threadIdx.x] += sh2[threadIdx.x + off];
        }
        __syncthreads();
    }
    if (threadIdx.x == 0) {
        float mean = sh[0] * (1.0f / GRP_ELEMS);
        float var  = sh2[0] * (1.0f / GRP_ELEMS) - mean * mean;
        g_mean[grp] = mean;
        g_rstd[grp] = rsqrtf(var + EPS_GN);
    }
}

// ---------------- fused GroupNorm-apply + transpose + fp16 hi/lo split ----------------
__global__ void gn_split_kernel(const float* __restrict__ x,
                                const float* __restrict__ gamma,
                                const float* __restrict__ beta) {
    __shared__ float sm[32][33];
    int p0 = blockIdx.x * 32, c0 = blockIdx.y * 32, b = blockIdx.z;
    int tx = threadIdx.x, ty = threadIdx.y;     // (32, 8)
    #pragma unroll
    for (int i = 0; i < 4; i++) {
        int c = c0 + ty + i*8;
        int grp = b*NG + (c >> 4);
        float m = g_mean[grp], r = g_rstd[grp];
        float ga = gamma[c], be = beta[c];
        size_t o = (size_t)b*C*HW + (size_t)c*HW + p0 + tx;
        float v = (x[o] - m) * r * ga + be;
        g_xn[o] = v;
        sm[ty + i*8][tx] = v;
    }
    __syncthreads();
    #pragma unroll
    for (int i = 0; i < 4; i++) {
        int p = p0 + ty + i*8;
        float v = sm[tx][ty + i*8];
        size_t o = (size_t)(b*HW + p) * C + c0 + tx;
        __half h = __float2half(v);
        g_x16h[o] = h;
        g_x16l[o] = __float2half(v - __half2float(h));
    }
}

// ---------------- weights -> fp16 ----------------
__global__ void split_w_kernel(const float* __restrict__ Wq, const float* __restrict__ Wk,
                               const float* __restrict__ Wv, const float* __restrict__ Wp) {
    int idx = blockIdx.x * 256 + threadIdx.x;   // < 2*C*C
    int wsel = idx >> 18;
    int off  = idx & (C*C - 1);
    g_w16qk[idx] = __float2half((wsel == 0) ? Wq[off] : Wk[off]);
    g_w16[idx]   = __float2half((wsel == 0) ? Wv[off] : Wp[off]);
}

// ======= QK GEMM 2-term fp16: 128 threads, 2 CTAs/SM, GBK=32, 2-stage =======
// Y[m, 0..1023] = (A_hi + A_lo) @ [Wq;Wk]16^T
#define GBM 128
#define GBN 128
#define GBK3 32
#define NCH3 (C/GBK3)        // 16
#define ASTR3 80
#define OFF3_AL 10240        // 128*80
#define OFF3_B  20480
#define STG3 30720
#define SMEM3 (2*STG3)       // 61440 -> 2 CTAs/SM

__device__ __forceinline__ void load_stage3(uint32_t sb,
        const __half* Ah, const __half* Al, const __half* Bw,
        int m0, int n0, int k0, int tid) {
    #pragma unroll
    for (int i = 0; i < 4; i++) {
        int q = tid + i*128;
        int r = q >> 2, c = q & 3;
        uint32_t d = sb + r*ASTR3 + c*16;
        size_t gA = (size_t)(m0 + r) * C + k0 + c*8;
        size_t gB = (size_t)(n0 + r) * C + k0 + c*8;
        CP_ASYNC16(d, Ah + gA);
        CP_ASYNC16(d + OFF3_AL, Al + gA);
        CP_ASYNC16(d + OFF3_B, Bw + gB);
    }
}

__global__ __launch_bounds__(128, 2)
void tc_gemmqk(const __half* __restrict__ Ah, const __half* __restrict__ Al,
               const __half* __restrict__ Bw, float* __restrict__ Y) {
    extern __shared__ char smc[];
    const uint32_t smb = smem_u32(smc);
    const int tid = threadIdx.x;
    const int lane = tid & 31, wid = tid >> 5;
    const int wm = wid & 1, wn = wid >> 1;        // 2x2 warps, warp tile 64x64
    const int n0 = blockIdx.x * GBN;
    const int m0 = blockIdx.y * GBM;

    float acc[4][8][4];
    #pragma unroll
    for (int a = 0; a < 4; a++)
        #pragma unroll
        for (int b = 0; b < 8; b++)
            #pragma unroll
            for (int c = 0; c < 4; c++) acc[a][b][c] = 0.f;

    const uint32_t aOff = (wm*64 + (lane & 15)) * ASTR3 + (lane >> 4) * 16;
    const uint32_t bOff = OFF3_B + (wn*64 + (lane & 7) + ((lane >> 4) & 1) * 8) * ASTR3
                        + ((lane >> 3) & 1) * 16;

    load_stage3(smb, Ah, Al, Bw, m0, n0, 0, tid);
    CP_COMMIT();
    load_stage3(smb + STG3, Ah, Al, Bw, m0, n0, GBK3, tid);
    CP_COMMIT();

    for (int ch = 0; ch < NCH3; ch++) {
        if (ch < NCH3 - 1) { CP_WAIT(1); } else { CP_WAIT(0); }
        __syncthreads();
        const uint32_t sb = smb + (ch & 1) * STG3;
        #pragma unroll
        for (int ks = 0; ks < 2; ks++) {
            uint32_t ah[4][4], al[4][4], bh[4][4];
            #pragma unroll
            for (int mt = 0; mt < 4; mt++) {
                ldsm4(ah[mt], sb + aOff + mt * (16*ASTR3) + ks * 32);
                ldsm4(al[mt], sb + OFF3_AL + aOff + mt * (16*ASTR3) + ks * 32);
            }
            #pragma unroll
            for (int np = 0; np < 4; np++)
                ldsm4(bh[np], sb + bOff + np * (16*ASTR3) + ks * 32);
            #pragma unroll
            for (int mt = 0; mt < 4; mt++)
                #pragma unroll
                for (int nt = 0; nt < 8; nt++)
                    hmma_f16(acc[mt][nt], ah[mt], &bh[nt >> 1][(nt & 1) * 2]);
            #pragma unroll
            for (int mt = 0; mt < 4; mt++)
                #pragma unroll
                for (int nt = 0; nt < 8; nt++)
                    hmma_f16(acc[mt][nt], al[mt], &bh[nt >> 1][(nt & 1) * 2]);
        }
        __syncthreads();
        if (ch + 2 < NCH3) {
            load_stage3(smb + (ch & 1) * STG3, Ah, Al, Bw, m0, n0, (ch + 2) * GBK3, tid);
            CP_COMMIT();
        }
    }

    const int mrow = wm*64 + (lane >> 2);
    const int ncol = n0 + wn*64 + 2*(lane & 3);
    #pragma unroll
    for (int mt = 0; mt < 4; mt++)
        #pragma unroll
        for (int nt = 0; nt < 8; nt++) {
            int r = m0 + mrow + mt*16;
            int cq = ncol + nt*8;
            float2 v0 = make_float2(acc[mt][nt][0], acc[mt][nt][1]);
            float2 v1 = make_float2(acc[mt][nt][2], acc[mt][nt][3]);
            *(float2*)&Y[(size_t)r * 1024 + cq]       = v0;
            *(float2*)&Y[(size_t)(r + 8) * 1024 + cq] = v1;
        }
}

// ======= GEMM 1-term fp16: 128 threads, 2 CTAs/SM, GBK=64, 2-stage =======
#define GBK1 64
#define NCH1 (C/GBK1)        // 8
#define ASTR1 144
#define OFF1_B 18432         // 128*144
#define STG1 36864
#define SMEM1 (2*STG1)       // 73728 -> 2 CTAs/SM

__device__ __forceinline__ void load_stage1(uint32_t sb,
        const __half* Aw, const __half* Bw,
        int m0, int n0, int k0, int tid) {
    #pragma unroll
    for (int i = 0; i < 8; i++) {
        int q = tid + i*128;
        int r = q >> 3, c = q & 7;
        uint32_t d = sb + r*ASTR1 + c*16;
        size_t gA = (size_t)(m0 + r) * C + k0 + c*8;
        size_t gB = (size_t)(n0 + r) * C + k0 + c*8;
        CP_ASYNC16(d, Aw + gA);
        CP_ASYNC16(d + OFF1_B, Bw + gB);
    }
}

template<int MODE>
__global__ __launch_bounds__(128, 2)
void tc_gemm1(const __half* __restrict__ Aw, const __half* __restrict__ Bw,
              float* __restrict__ Y, const float* __restrict__ bias,
              const float* __restrict__ resid) {
    extern __shared__ char smc[];
    const uint32_t smb = smem_u32(smc);
    const int tid = threadIdx.x;
    const int lane = tid & 31, wid = tid >> 5;
    const int wm = wid & 1, wn = wid >> 1;        // 2x2 warps, warp tile 64x64
    const int n0 = blockIdx.x * GBN;
    const int m0 = blockIdx.y * GBM;
    const int bb = m0 / HW;
    const int p0 = m0 % HW;

    float acc[4][8][4];
    #pragma unroll
    for (int a = 0; a < 4; a++)
        #pragma unroll
        for (int b = 0; b < 8; b++)
            #pragma unroll
            for (int c = 0; c < 4; c++) acc[a][b][c] = 0.f;

    const uint32_t aOff = (wm*64 + (lane & 15)) * ASTR1 + (lane >> 4) * 16;
    const uint32_t bOff = OFF1_B + (wn*64 + (lane & 7) + ((lane >> 4) & 1) * 8) * ASTR1
                        + ((lane >> 3) & 1) * 16;

    load_stage1(smb, Aw, Bw, m0, n0, 0, tid);
    CP_COMMIT();
    load_stage1(smb + STG1, Aw, Bw, m0, n0, GBK1, tid);
    CP_COMMIT();

    for (int ch = 0; ch < NCH1; ch++) {
        if (ch < NCH1 - 1) { CP_WAIT(1); } else { CP_WAIT(0); }
        __syncthreads();
        const uint32_t sb = smb + (ch & 1) * STG1;
        #pragma unroll
        for (int ks = 0; ks < 4; ks++) {
            uint32_t ah[4][4], bh[4][4];
            #pragma unroll
            for (int mt = 0; mt < 4; mt++)
                ldsm4(ah[mt], sb + aOff + mt * (16*ASTR1) + ks * 32);
            #pragma unroll
            for (int np = 0; np < 4; np++)
                ldsm4(bh[np], sb + bOff + np * (16*ASTR1) + ks * 32);
            #pragma unroll
            for (int mt = 0; mt < 4; mt++)
                #pragma unroll
                for (int nt = 0; nt < 8; nt++)
                    hmma_f16(acc[mt][nt], ah[mt], &bh[nt >> 1][(nt & 1) * 2]);
        }
        __syncthreads();
        if (ch + 2 < NCH1) {
            load_stage1(smb + (ch & 1) * STG1, Aw, Bw, m0, n0, (ch + 2) * GBK1, tid);
            CP_COMMIT();
        }
    }

    const int mrow = wm*64 + (lane >> 2);
    const int ncol = n0 + wn*64 + 2*(lane & 3);
    if (MODE == 0) {
        #pragma unroll
        for (int mt = 0; mt < 4; mt++)
            #pragma unroll
            for (int nt = 0; nt < 8; nt++) {
                int r = m0 + mrow + mt*16;
                int cq = ncol + nt*8;
                float2 v0 = make_float2(acc[mt][nt][0], acc[mt][nt][1]);
                float2 v1 = make_float2(acc[mt][nt][2], acc[mt][nt][3]);
                *(float2*)&Y[(size_t)r * C + cq]       = v0;
                *(float2*)&Y[(size_t)(r + 8) * C + cq] = v1;
            }
    } else {
        #pragma unroll
        for (int mt = 0; mt < 4; mt++)
            #pragma unroll
            for (int nt = 0; nt < 8; nt++) {
                int p = p0 + mrow + mt*16;
                int j = ncol + nt*8;
                float bj0 = bias[j], bj1 = bias[j + 1];
                size_t a00 = (size_t)bb*C*HW + (size_t)j*HW + p;
                Y[a00]          = acc[mt][nt][0] + bj0 + resid[a00];
                Y[a00 + HW]     = acc[mt][nt][1] + bj1 + resid[a00 + HW];
                Y[a00 + 8]      = acc[mt][nt][2] + bj0 + resid[a00 + 8];
                Y[a00 + HW + 8] = acc[mt][nt][3] + bj1 + resid[a00 + HW + 8];
            }
    }
}

// ---------------- dots: warp per (b,n); all 64 (i,j) pairs ----------------
__global__ void dots_kernel() {
    __shared__ float sQ[8][512];
    __shared__ float sK[8][512];
    int w = threadIdx.x >> 5, lane = threadIdx.x & 31;
    int m = blockIdx.x * 8 + w;                 // < 32768
    int b = m >> 12, n = m & 4095;
    const float4* q4 = (const float4*)(g_qk + (size_t)m * 1024);
    const float4* k4 = q4 + 128;                // K half of the row
    #pragma unroll
    for (int i = 0; i < 4; i++) {
        ((float4*)sQ[w])[lane + i*32] = q4[lane + i*32];
        ((float4*)sK[w])[lane + i*32] = k4[lane + i*32];
    }
    __syncwarp();
    #pragma unroll
    for (int t = 0; t < 2; t++) {
        int p = lane + t*32;                    // 0..63
        int i = p >> 3, j = p & 7;
        const float* qi = &sQ[w][i * HD];
        const float* kj = &sK[w][j * HD];
        float acc = 0.f;
        #pragma unroll
        for (int d = 0; d < HD; d++) acc += qi[d] * kj[d];
        g_att[(size_t)(b*64 + p) * HW + n] = acc * SCALE_ATT;
    }
}

// ---------------- softmax over n per (b,i,j) row, in place ----------------
__global__ void softmax_kernel() {
    float* row = g_att + (size_t)blockIdx.x * HW;
    __shared__ float sh[256];
    int tid = threadIdx.x;

    float mx = -1e30f;
    for (int n = tid; n < HW; n += 256) mx = fmaxf(mx, row[n]);
    sh[tid] = mx; __syncthreads();
    for (int off = 128; off > 0; off >>= 1) {
        if (tid < off) sh[tid] = fmaxf(sh[tid], sh[tid + off]);
        __syncthreads();
    }
    mx = sh[0]; __syncthreads();

    float sum = 0.f;
    for (int n = tid; n < HW; n += 256) sum += __expf(row[n] - mx);
    sh[tid] = sum; __syncthreads();
    for (int off = 128; off > 0; off >>= 1) {
        if (tid < off) sh[tid] += sh[tid + off];
        __syncthreads();
    }
    float inv = 1.f / sh[0];

    for (int n = tid; n < HW; n += 256) row[n] = __expf(row[n] - mx) * inv;
}

// ---------------- transpose att: (b, ij, n) -> (b, n, ij) ----------------
__global__ void att_tr_kernel() {
    __shared__ float sm[64][65];
    int n0 = blockIdx.x * 64, b = blockIdx.y;
    int tx = threadIdx.x, ty = threadIdx.y;     // (64, 8)
    #pragma unroll
    for (int i = 0; i < 8; i++) {
        int ij = ty + i*8;
        sm[ij][tx] = g_att[((size_t)(b*64 + ij)) * HW + n0 + tx];
    }
    __syncthreads();
    #pragma unroll
    for (int i = 0; i < 8; i++) {
        int n = n0 + ty + i*8;
        g_att_t[((size_t)b*HW + n) * 64 + tx] = sm[tx][ty + i*8];
    }
}

// ---------------- attv: coalesced att_t reads; fp16 out ----------------
__global__ void attv_kernel() {
    size_t idx = (size_t)blockIdx.x * 256 + threadIdx.x;  // < M_TOT*C
    int m  = (int)(idx >> 9);
    int cc = (int)(idx & 511);
    int i = cc >> 6, d = cc & 63;
    const float* att = g_att_t + (size_t)m * 64 + i*8;    // contiguous 8 floats
    const float* v   = g_v + (size_t)m * C + d;
    float acc = 0.f;
    #pragma unroll
    for (int j = 0; j < NHEAD; j++)
        acc += att[j] * v[j * HD];
    g_ao_h[idx] = __float2half(acc);
}

// ---------------- launch (single stream, serial) ----------------
extern "C" void kernel_launch(void* const* d_in, const int* in_sizes, int n_in,
                              void* d_out, int out_size) {
    const float* x     = (const float*)d_in[0];
    const float* gamma = (const float*)d_in[1];
    const float* beta  = (const float*)d_in[2];
    const float* Wq    = (const float*)d_in[3];
    const float* Wk    = (const float*)d_in[4];
    const float* Wv    = (const float*)d_in[5];
    const float* Wp    = (const float*)d_in[6];
    const float* bp    = (const float*)d_in[7];
    float* out = (float*)d_out;

    float *p_xn, *p_qk, *p_v;
    __half *p_x16h, *p_x16l, *p_w16qk, *p_w16, *p_aoh;
    cudaGetSymbolAddress((void**)&p_xn,    g_xn);
    cudaGetSymbolAddress((void**)&p_qk,    g_qk);
    cudaGetSymbolAddress((void**)&p_v,     g_v);
    cudaGetSymbolAddress((void**)&p_x16h,  g_x16h);
    cudaGetSymbolAddress((void**)&p_x16l,  g_x16l);
    cudaGetSymbolAddress((void**)&p_w16qk, g_w16qk);
    cudaGetSymbolAddress((void**)&p_w16,   g_w16);
    cudaGetSymbolAddress((void**)&p_aoh,   g_ao_h);

    cudaFuncSetAttribute(tc_gemmqk,   cudaFuncAttributeMaxDynamicSharedMemorySize, SMEM3);
    cudaFuncSetAttribute(tc_gemm1<0>, cudaFuncAttributeMaxDynamicSharedMemorySize, SMEM1);
    cudaFuncSetAttribute(tc_gemm1<1>, cudaFuncAttributeMaxDynamicSharedMemorySize, SMEM1);

    gn_stats_kernel<<<B*NG, 512>>>(x);
    gn_split_kernel<<<dim3(HW/32, C/32, B), dim3(32, 8)>>>(x, gamma, beta);
    split_w_kernel<<<2*C*C/256, 256>>>(Wq, Wk, Wv, Wp);

    // fused Q|K GEMM: N = 1024, fp16 2-term
    dim3 g3(1024/GBN, M_TOT/GBM);   // (8, 256) = 2048 CTAs
    tc_gemmqk<<<g3, 128, SMEM3>>>(p_x16h, p_x16l, p_w16qk, p_qk);

    // V GEMM (fp16 1-term)
    dim3 g2(C/GBN, M_TOT/GBM);      // (4, 256) = 1024 CTAs
    tc_gemm1<0><<<g2, 128, SMEM1>>>(p_x16h, p_w16, p_v, nullptr, nullptr);

    dots_kernel<<<M_TOT/8, 256>>>();
    softmax_kernel<<<B*NHEAD*NHEAD, 256>>>();
    att_tr_kernel<<<dim3(HW/64, B), dim3(64, 8)>>>();
    attv_kernel<<<(unsigned)(M_TOT*(size_t)C/256), 256>>>();

    // proj GEMM (fp16 1-term) + bias + residual
    tc_gemm1<1><<<g2, 128, SMEM1>>>(p_aoh, p_w16 + (size_t)C*C, out, bp, p_xn);
}